// round 10
// baseline (speedup 1.0000x reference)
#include <cuda_runtime.h>
#include <cuda_fp16.h>
#include <cstdint>

#define H 256
#define MAXROWS 50000
#define NMAX 50048
#define EMAX 300000
#define LN_EPS 1e-5f

// ---------------------------------------------------------------------------
// Scratch (__device__ globals: allocation-free rule)
// ---------------------------------------------------------------------------
__device__ float g_agg[MAXROWS * H];
__device__ __half g_wt[4][H * H];        // transposed fp16 weights
__device__ int   g_deg[NMAX];
__device__ int   g_cnt[NMAX];
__device__ int   g_off[NMAX + 1];
__device__ int   g_csrc[EMAX];
__device__ float g_cea[EMAX];

// ---------------------------------------------------------------------------
// PTX helpers
// ---------------------------------------------------------------------------
__device__ __forceinline__ uint32_t smem_u32(const void* p) {
    uint32_t a;
    asm("{ .reg .u64 t; cvta.to.shared.u64 t, %1; cvt.u32.u64 %0, t; }"
        : "=r"(a) : "l"(p));
    return a;
}
__device__ __forceinline__ void ldsm_x4(uint32_t r[4], uint32_t addr) {
    asm volatile("ldmatrix.sync.aligned.m8n8.x4.shared.b16 {%0,%1,%2,%3}, [%4];"
                 : "=r"(r[0]), "=r"(r[1]), "=r"(r[2]), "=r"(r[3]) : "r"(addr));
}
__device__ __forceinline__ void mma_f16(float c[4],
                                        const uint32_t a[4],
                                        uint32_t b0, uint32_t b1) {
    asm volatile(
        "mma.sync.aligned.m16n8k16.row.col.f32.f16.f16.f32 "
        "{%0,%1,%2,%3}, {%4,%5,%6,%7}, {%8,%9}, {%0,%1,%2,%3};"
        : "+f"(c[0]), "+f"(c[1]), "+f"(c[2]), "+f"(c[3])
        : "r"(a[0]), "r"(a[1]), "r"(a[2]), "r"(a[3]), "r"(b0), "r"(b1));
}
__device__ __forceinline__ void cp16(uint32_t dst, const void* src) {
    asm volatile("cp.async.ca.shared.global [%0], [%1], 16;"
                 :: "r"(dst), "l"(src) : "memory");
}
#define CP_COMMIT() asm volatile("cp.async.commit_group;" ::: "memory")
#define CP_WAIT1()  asm volatile("cp.async.wait_group 1;" ::: "memory")
#define CP_WAIT0()  asm volatile("cp.async.wait_group 0;" ::: "memory")

__device__ __forceinline__ uint32_t pack2h(float a, float b) {
    __half2 h = __floats2half2_rn(a, b);
    return *(uint32_t*)&h;
}

// ---------------------------------------------------------------------------
// SMEM layout for fused_gine (bytes)
// ---------------------------------------------------------------------------
#define SM_A(st)   ((st) * 5120)
#define SM_W(st)   (10240 + (st) * 20480)
#define SM_H       51200
#define SM_B1      92160
#define SM_B2      93184
#define SM_G       94208
#define SM_BETA    95232
#define SM_PSUM    96256
#define SM_PSQ     96512
#define SMEM_T     96768

// ---------------------------------------------------------------------------
// Weight prep (4 weights, one launch): Wt[n][k] = fp16(W[k][n])
// ---------------------------------------------------------------------------
__global__ void wprep4_kernel(const float* __restrict__ W0,
                              const float* __restrict__ W1,
                              const float* __restrict__ W2,
                              const float* __restrict__ W3,
                              __half* __restrict__ base) {
    __shared__ float tile[32][33];
    const int which = blockIdx.x >> 6;
    const float* W = (which == 0) ? W0 : (which == 1) ? W1
                   : (which == 2) ? W2 : W3;
    __half* hi = base + (size_t)which * H * H;
    const int b  = blockIdx.x & 63;
    const int tx = threadIdx.x & 31;
    const int ty = threadIdx.x >> 5;
    const int bx = b & 7;
    const int by = b >> 3;
#pragma unroll
    for (int i = 0; i < 4; i++)
        tile[ty + i * 8][tx] = W[(by * 32 + ty + i * 8) * H + bx * 32 + tx];
    __syncthreads();
#pragma unroll
    for (int i = 0; i < 4; i++) {
        float v = tile[tx][ty + i * 8];
        int n = bx * 32 + ty + i * 8;
        int k = by * 32 + tx;
        hi[n * H + k] = __float2half_rn(v);
    }
}

// ---------------------------------------------------------------------------
// CSR build kernels
// ---------------------------------------------------------------------------
__global__ void zero2_kernel(int* __restrict__ a, int* __restrict__ b, int n) {
    int i = blockIdx.x * 256 + threadIdx.x;
    if (i < n) { a[i] = 0; b[i] = 0; }
}

__global__ void hist_kernel(const int* __restrict__ dst,
                            int* __restrict__ deg, int E) {
    int e = blockIdx.x * 256 + threadIdx.x;
    if (e < E) atomicAdd(&deg[__ldg(dst + e)], 1);
}

// single-block exclusive scan over n<=50048 ints
__global__ void scan_kernel(const int* __restrict__ deg,
                            int* __restrict__ off, int n) {
    __shared__ int ss[1024];
    int t = threadIdx.x;
    int per = (n + 1023) >> 10;
    int st = t * per;
    int en = st + per; if (en > n) en = n;
    int s = 0;
    for (int i = st; i < en; i++) s += __ldg(deg + i);
    ss[t] = s;
    __syncthreads();
    for (int o = 1; o < 1024; o <<= 1) {
        int v = (t >= o) ? ss[t - o] : 0;
        __syncthreads();
        ss[t] += v;
        __syncthreads();
    }
    int base = (t > 0) ? ss[t - 1] : 0;
    for (int i = st; i < en; i++) {
        off[i] = base;
        base += __ldg(deg + i);
    }
    if (t == 1023) off[n] = ss[1023];
}

__global__ void fill_kernel(const int* __restrict__ src,
                            const int* __restrict__ dst,
                            const float* __restrict__ ea,
                            const int* __restrict__ off,
                            int* __restrict__ cnt,
                            int* __restrict__ csrc,
                            float* __restrict__ cea, int E) {
    int e = blockIdx.x * 256 + threadIdx.x;
    if (e >= E) return;
    int d = __ldg(dst + e);
    int pos = __ldg(off + d) + atomicAdd(&cnt[d], 1);
    csrc[pos] = __ldg(src + e);
    cea[pos]  = __ldg(ea + e);
}

// ---------------------------------------------------------------------------
// Aggregate: agg[r] = sum_{edges->r} relu(x_src + ea*We + be). Warp per row.
// Covers all rows (zero-degree rows write zeros) -> no zero_kernel needed.
// ---------------------------------------------------------------------------
__global__ void agg_kernel(const float* __restrict__ xsrc,
                           const int* __restrict__ off,
                           const int* __restrict__ csrc,
                           const float* __restrict__ cea,
                           const float* __restrict__ We,
                           const float* __restrict__ be,
                           float* __restrict__ agg, int M) {
    int r = blockIdx.x * 8 + (threadIdx.x >> 5);
    if (r >= M) return;
    int lane = threadIdx.x & 31;
    int col = lane * 8;

    float4 w0 = __ldg((const float4*)(We + col));
    float4 w1 = __ldg((const float4*)(We + col + 4));
    float4 b0 = __ldg((const float4*)(be + col));
    float4 b1 = __ldg((const float4*)(be + col + 4));

    float acc[8] = {0.f, 0.f, 0.f, 0.f, 0.f, 0.f, 0.f, 0.f};

    int i  = __ldg(off + r);
    int s1 = __ldg(off + r + 1);

    int   sn = 0;
    float an = 0.f;
    if (i < s1) { sn = __ldg(csrc + i); an = __ldg(cea + i); }

    while (i < s1) {
        int s = sn; float a = an;
        i++;
        if (i < s1) { sn = __ldg(csrc + i); an = __ldg(cea + i); }

        const float4* xp = (const float4*)(xsrc + (size_t)s * H + col);
        float4 x0 = xp[0], x1 = xp[1];
        acc[0] += fmaxf(x0.x + fmaf(a, w0.x, b0.x), 0.f);
        acc[1] += fmaxf(x0.y + fmaf(a, w0.y, b0.y), 0.f);
        acc[2] += fmaxf(x0.z + fmaf(a, w0.z, b0.z), 0.f);
        acc[3] += fmaxf(x0.w + fmaf(a, w0.w, b0.w), 0.f);
        acc[4] += fmaxf(x1.x + fmaf(a, w1.x, b1.x), 0.f);
        acc[5] += fmaxf(x1.y + fmaf(a, w1.y, b1.y), 0.f);
        acc[6] += fmaxf(x1.z + fmaf(a, w1.z, b1.z), 0.f);
        acc[7] += fmaxf(x1.w + fmaf(a, w1.w, b1.w), 0.f);
    }

    float* o = agg + (size_t)r * H + col;
    *(float4*)(o)     = make_float4(acc[0], acc[1], acc[2], acc[3]);
    *(float4*)(o + 4) = make_float4(acc[4], acc[5], acc[6], acc[7]);
}

// ---------------------------------------------------------------------------
// Fused GINE MLP: out = LN( relu((x+agg)@Wa + ba) @ Wb + bb + x ) * g + beta
// Pure fp16 single-pass MMA. Tile 64M x 256N, BK=32, 8 warps, 2 CTAs/SM.
// ---------------------------------------------------------------------------
__global__ __launch_bounds__(256, 2) void fused_gine(
    const float* __restrict__ X, const float* __restrict__ AGG,
    const __half* __restrict__ Wa, const __half* __restrict__ Wb,
    const float* __restrict__ ba, const float* __restrict__ bb,
    const float* __restrict__ gln, const float* __restrict__ bln,
    float* __restrict__ C, int M)
{
    extern __shared__ char sm[];
    const uint32_t sb = smem_u32(sm);

    const int t = threadIdx.x;
    const int lane = t & 31;
    const int wid = t >> 5;
    const int wm = wid & 1;
    const int wn = wid >> 1;
    const int bm = blockIdx.x * 64;

    float* b1S  = (float*)(sm + SM_B1);
    float* b2S  = (float*)(sm + SM_B2);
    float* gS   = (float*)(sm + SM_G);
    float* bS   = (float*)(sm + SM_BETA);
    float* psum = (float*)(sm + SM_PSUM);
    float* psq  = (float*)(sm + SM_PSQ);

    b1S[t] = ba[t];
    b2S[t] = bb[t];
    gS[t]  = gln[t];
    bS[t]  = bln[t];
    if (t < 64) { psum[t] = 0.f; psq[t] = 0.f; }

    float c[2][8][4];
#pragma unroll
    for (int i = 0; i < 2; i++)
#pragma unroll
        for (int j = 0; j < 8; j++)
#pragma unroll
            for (int e = 0; e < 4; e++) c[i][j][e] = 0.f;

    const int row_a = t >> 2;
    const int kq_a  = t & 3;
    const int grow_a = bm + row_a;
    const bool aval = (grow_a < M);

    auto lda = [&](int ck, float4& v0, float4& v1) {
        if (aval) {
            size_t off = (size_t)grow_a * H + ck * 32 + kq_a * 8;
            const float4* p = (const float4*)(X + off);
            const float4* q = (const float4*)(AGG + off);
            float4 a0 = p[0], a1 = p[1];
            float4 u0 = q[0], u1 = q[1];
            v0.x = a0.x + u0.x; v0.y = a0.y + u0.y;
            v0.z = a0.z + u0.z; v0.w = a0.w + u0.w;
            v1.x = a1.x + u1.x; v1.y = a1.y + u1.y;
            v1.z = a1.z + u1.z; v1.w = a1.w + u1.w;
        } else {
            v0 = make_float4(0.f, 0.f, 0.f, 0.f);
            v1 = v0;
        }
    };
    auto sts_a = [&](int st, float4 v0, float4 v1) {
        uint32_t hv[4];
        hv[0] = pack2h(v0.x, v0.y);
        hv[1] = pack2h(v0.z, v0.w);
        hv[2] = pack2h(v1.x, v1.y);
        hv[3] = pack2h(v1.z, v1.w);
        uint32_t o = (uint32_t)(row_a * 80 + kq_a * 16);
        *(uint4*)(sm + SM_A(st) + o) = make_uint4(hv[0], hv[1], hv[2], hv[3]);
    };
    auto cpw = [&](const __half* W, int ck, int st) {
        const __half* s = W + (size_t)t * H + ck * 32;
        uint32_t d = sb + SM_W(st) + t * 80;
#pragma unroll
        for (int q = 0; q < 4; q++) cp16(d + q * 16, s + q * 8);
    };

    const uint32_t a_off = (uint32_t)((lane & 15) * 80 + (lane >> 4) * 16);
    const uint32_t w_off = (uint32_t)((wn * 64 + (lane & 7) + ((lane >> 4) * 8)) * 80
                                      + (((lane >> 3) & 1) * 16));

    auto compute = [&](uint32_t aBase, uint32_t wBase) {
        const uint32_t ah_base = aBase + (uint32_t)(wm * 2560) + a_off;
        const uint32_t wh_base = wBase + w_off;
#pragma unroll
        for (int ks = 0; ks < 2; ks++) {
            uint32_t ah0[4], ah1[4];
            uint32_t ab = ah_base + ks * 32;
            ldsm_x4(ah0, ab);
            ldsm_x4(ah1, ab + 1280);
            uint32_t bf[4][4];
            uint32_t wb = wh_base + ks * 32;
#pragma unroll
            for (int n4 = 0; n4 < 4; n4++) ldsm_x4(bf[n4], wb + n4 * 1280);
#pragma unroll
            for (int n4 = 0; n4 < 4; n4++) {
                const int nf = n4 * 2;
                mma_f16(c[0][nf],     ah0, bf[n4][0], bf[n4][1]);
                mma_f16(c[0][nf + 1], ah0, bf[n4][2], bf[n4][3]);
                mma_f16(c[1][nf],     ah1, bf[n4][0], bf[n4][1]);
                mma_f16(c[1][nf + 1], ah1, bf[n4][2], bf[n4][3]);
            }
        }
    };

    const int qrow = lane >> 2;
    const int qcol = lane & 3;

    // =================== Phase A: acc1 = (X+AGG) @ Wa ===================
    float4 p0, p1, n0, n1;
    lda(0, p0, p1);
    cpw(Wa, 0, 0);
    CP_COMMIT();

#pragma unroll 1
    for (int ck = 0; ck < 8; ck++) {
        const int st = ck & 1;
        sts_a(st, p0, p1);
        if (ck < 7) {
            lda(ck + 1, n0, n1);
            cpw(Wa, ck + 1, st ^ 1);
            CP_COMMIT();
            CP_WAIT1();
        } else {
            CP_WAIT0();
        }
        __syncthreads();
        compute(sb + SM_A(st), sb + SM_W(st));
        __syncthreads();
        p0 = n0; p1 = n1;
    }

    // ---- epilogue 1: h = relu(acc1 + ba) -> smem fp16 (A layout) ----
#pragma unroll
    for (int mf = 0; mf < 2; mf++)
#pragma unroll
        for (int rh = 0; rh < 2; rh++) {
            int r = wm * 32 + mf * 16 + rh * 8 + qrow;
#pragma unroll
            for (int nf = 0; nf < 8; nf++) {
                int kcol = wn * 64 + nf * 8 + qcol * 2;
                float z0 = fmaxf(c[mf][nf][rh * 2]     + b1S[kcol],     0.f);
                float z1 = fmaxf(c[mf][nf][rh * 2 + 1] + b1S[kcol + 1], 0.f);
                uint32_t off = (uint32_t)((kcol >> 5) * 5120 + r * 80
                                          + (kcol & 31) * 2);
                *(uint32_t*)(sm + SM_H + off) = pack2h(z0, z1);
            }
        }

#pragma unroll
    for (int i = 0; i < 2; i++)
#pragma unroll
        for (int j = 0; j < 8; j++)
#pragma unroll
            for (int e = 0; e < 4; e++) c[i][j][e] = 0.f;

    // =================== Phase B: acc2 = h @ Wb =========================
    cpw(Wb, 0, 0);
    CP_COMMIT();

#pragma unroll 1
    for (int ck = 0; ck < 8; ck++) {
        const int st = ck & 1;
        if (ck < 7) {
            cpw(Wb, ck + 1, st ^ 1);
            CP_COMMIT();
            CP_WAIT1();
        } else {
            CP_WAIT0();
        }
        __syncthreads();
        compute(sb + SM_H + ck * 5120, sb + SM_W(st));
        __syncthreads();
    }

    // ---- epilogue 2: LN(acc2 + bb + X) * g + beta ----
#pragma unroll
    for (int mf = 0; mf < 2; mf++)
#pragma unroll
        for (int rh = 0; rh < 2; rh++) {
            int r = wm * 32 + mf * 16 + rh * 8 + qrow;
            int grow = bm + r;
            float su = 0.f, sq = 0.f;
            if (grow < M) {
                const float* rrow = X + (size_t)grow * H;
#pragma unroll
                for (int nf = 0; nf < 8; nf++) {
                    int col = wn * 64 + nf * 8 + qcol * 2;
                    float2 rv = *(const float2*)(rrow + col);
                    float z0 = c[mf][nf][rh * 2]     + b2S[col]     + rv.x;
                    float z1 = c[mf][nf][rh * 2 + 1] + b2S[col + 1] + rv.y;
                    c[mf][nf][rh * 2]     = z0;
                    c[mf][nf][rh * 2 + 1] = z1;
                    su += z0 + z1;
                    sq += z0 * z0 + z1 * z1;
                }
            }
            su += __shfl_xor_sync(0xFFFFFFFFu, su, 1);
            su += __shfl_xor_sync(0xFFFFFFFFu, su, 2);
            sq += __shfl_xor_sync(0xFFFFFFFFu, sq, 1);
            sq += __shfl_xor_sync(0xFFFFFFFFu, sq, 2);
            if (qcol == 0 && grow < M) {
                atomicAdd(&psum[r], su);
                atomicAdd(&psq[r], sq);
            }
        }
    __syncthreads();
#pragma unroll
    for (int mf = 0; mf < 2; mf++)
#pragma unroll
        for (int rh = 0; rh < 2; rh++) {
            int r = wm * 32 + mf * 16 + rh * 8 + qrow;
            int grow = bm + r;
            if (grow >= M) continue;
            float mu = psum[r] * (1.f / 256.f);
            float var = psq[r] * (1.f / 256.f) - mu * mu;
            float rs = rsqrtf(var + LN_EPS);
            float* crow = C + (size_t)grow * H;
#pragma unroll
            for (int nf = 0; nf < 8; nf++) {
                int col = wn * 64 + nf * 8 + qcol * 2;
                float2 o;
                o.x = (c[mf][nf][rh * 2]     - mu) * rs * gS[col]     + bS[col];
                o.y = (c[mf][nf][rh * 2 + 1] - mu) * rs * gS[col + 1] + bS[col + 1];
                *(float2*)(crow + col) = o;
            }
        }
}

// ---------------------------------------------------------------------------
// launch
// ---------------------------------------------------------------------------
extern "C" void kernel_launch(void* const* d_in, const int* in_sizes, int n_in,
                              void* d_out, int out_size) {
    const float* x_var    = (const float*)d_in[0];
    const float* x_constr = (const float*)d_in[1];
    const int*   ei_v2c   = (const int*)  d_in[2];
    const int*   ei_c2v   = (const int*)  d_in[3];
    const float* ea       = (const float*)d_in[4];
    const float* We1 = (const float*)d_in[5];
    const float* be1 = (const float*)d_in[6];
    const float* W1a = (const float*)d_in[7];
    const float* b1a = (const float*)d_in[8];
    const float* W1b = (const float*)d_in[9];
    const float* b1b = (const float*)d_in[10];
    const float* We2 = (const float*)d_in[11];
    const float* be2 = (const float*)d_in[12];
    const float* W2a = (const float*)d_in[13];
    const float* b2a = (const float*)d_in[14];
    const float* W2b = (const float*)d_in[15];
    const float* b2b = (const float*)d_in[16];
    const float* g_constr    = (const float*)d_in[17];
    const float* beta_constr = (const float*)d_in[18];
    const float* g_var       = (const float*)d_in[19];
    const float* beta_var    = (const float*)d_in[20];

    const int NVr = in_sizes[0] / H;
    const int NCr = in_sizes[1] / H;
    const int Ecnt = in_sizes[4];

    float* agg;
    cudaGetSymbolAddress((void**)&agg, g_agg);
    __half* wt;
    cudaGetSymbolAddress((void**)&wt, g_wt);
    int *deg, *cnt, *off, *csrc;
    float *cea;
    cudaGetSymbolAddress((void**)&deg, g_deg);
    cudaGetSymbolAddress((void**)&cnt, g_cnt);
    cudaGetSymbolAddress((void**)&off, g_off);
    cudaGetSymbolAddress((void**)&csrc, g_csrc);
    cudaGetSymbolAddress((void**)&cea, g_cea);

    __half* wt1a = wt;
    __half* wt1b = wt + H * H;
    __half* wt2a = wt + 2 * H * H;
    __half* wt2b = wt + 3 * H * H;

    cudaFuncSetAttribute(fused_gine,
                         cudaFuncAttributeMaxDynamicSharedMemorySize, SMEM_T);

    float* out_var    = (float*)d_out;
    float* out_constr = (float*)d_out + (size_t)NVr * H;

    const int eb = (Ecnt + 255) / 256;

    wprep4_kernel<<<256, 256>>>(W1a, W1b, W2a, W2b, wt);

    // ---- stage 1: var -> constr ----
    {
        const int* src1 = ei_v2c;
        const int* dst1 = ei_v2c + Ecnt;
        zero2_kernel<<<(NCr + 255) / 256, 256>>>(deg, cnt, NCr);
        hist_kernel<<<eb, 256>>>(dst1, deg, Ecnt);
        scan_kernel<<<1, 1024>>>(deg, off, NCr);
        fill_kernel<<<eb, 256>>>(src1, dst1, ea, off, cnt, csrc, cea, Ecnt);
        agg_kernel<<<(NCr + 7) / 8, 256>>>(x_var, off, csrc, cea,
                                           We1, be1, agg, NCr);
        int gx = (NCr + 63) / 64;
        fused_gine<<<gx, 256, SMEM_T>>>(
            x_constr, agg, wt1a, wt1b, b1a, b1b,
            g_constr, beta_constr, out_constr, NCr);
    }

    // ---- stage 2: constr -> var (reads LN'd x_constr from d_out) ----
    {
        const int* src2 = ei_c2v;
        const int* dst2 = ei_c2v + Ecnt;
        zero2_kernel<<<(NVr + 255) / 256, 256>>>(deg, cnt, NVr);
        hist_kernel<<<eb, 256>>>(dst2, deg, Ecnt);
        scan_kernel<<<1, 1024>>>(deg, off, NVr);
        fill_kernel<<<eb, 256>>>(src2, dst2, ea, off, cnt, csrc, cea, Ecnt);
        agg_kernel<<<(NVr + 7) / 8, 256>>>(out_constr, off, csrc, cea,
                                           We2, be2, agg, NVr);
        int gx = (NVr + 63) / 64;
        fused_gine<<<gx, 256, SMEM_T>>>(
            x_var, agg, wt2a, wt2b, b2a, b2b,
            g_var, beta_var, out_var, NVr);
    }
}

// round 11
// speedup vs baseline: 1.2013x; 1.2013x over previous
#include <cuda_runtime.h>
#include <cuda_fp16.h>
#include <cstdint>

#define H 256
#define MAXROWS 50000
#define NMAX 50048
#define EMAX 300000
#define LN_EPS 1e-5f

// ---------------------------------------------------------------------------
// Scratch (__device__ globals: allocation-free rule)
// ---------------------------------------------------------------------------
__device__ float g_agg[MAXROWS * H];
__device__ __half g_wt[4][H * H];        // transposed fp16 weights
__device__ int   g_deg[NMAX];
__device__ int   g_cnt[NMAX];
__device__ int   g_off[NMAX + 1];
__device__ int   g_part[64];
__device__ int   g_csrc[EMAX];
__device__ float g_cea[EMAX];

// ---------------------------------------------------------------------------
// PTX helpers
// ---------------------------------------------------------------------------
__device__ __forceinline__ uint32_t smem_u32(const void* p) {
    uint32_t a;
    asm("{ .reg .u64 t; cvta.to.shared.u64 t, %1; cvt.u32.u64 %0, t; }"
        : "=r"(a) : "l"(p));
    return a;
}
__device__ __forceinline__ void ldsm_x4(uint32_t r[4], uint32_t addr) {
    asm volatile("ldmatrix.sync.aligned.m8n8.x4.shared.b16 {%0,%1,%2,%3}, [%4];"
                 : "=r"(r[0]), "=r"(r[1]), "=r"(r[2]), "=r"(r[3]) : "r"(addr));
}
__device__ __forceinline__ void mma_f16(float c[4],
                                        const uint32_t a[4],
                                        uint32_t b0, uint32_t b1) {
    asm volatile(
        "mma.sync.aligned.m16n8k16.row.col.f32.f16.f16.f32 "
        "{%0,%1,%2,%3}, {%4,%5,%6,%7}, {%8,%9}, {%0,%1,%2,%3};"
        : "+f"(c[0]), "+f"(c[1]), "+f"(c[2]), "+f"(c[3])
        : "r"(a[0]), "r"(a[1]), "r"(a[2]), "r"(a[3]), "r"(b0), "r"(b1));
}
__device__ __forceinline__ void cp16(uint32_t dst, const void* src) {
    asm volatile("cp.async.ca.shared.global [%0], [%1], 16;"
                 :: "r"(dst), "l"(src) : "memory");
}
#define CP_COMMIT() asm volatile("cp.async.commit_group;" ::: "memory")
#define CP_WAIT1()  asm volatile("cp.async.wait_group 1;" ::: "memory")
#define CP_WAIT0()  asm volatile("cp.async.wait_group 0;" ::: "memory")

__device__ __forceinline__ uint32_t pack2h(float a, float b) {
    __half2 h = __floats2half2_rn(a, b);
    return *(uint32_t*)&h;
}

// ---------------------------------------------------------------------------
// SMEM layout for fused_gine (bytes)
// ---------------------------------------------------------------------------
#define SM_A(st)   ((st) * 5120)
#define SM_W(st)   (10240 + (st) * 20480)
#define SM_H       51200
#define SM_B1      92160
#define SM_B2      93184
#define SM_G       94208
#define SM_BETA    95232
#define SM_PSUM    96256
#define SM_PSQ     96512
#define SMEM_T     96768

// ---------------------------------------------------------------------------
// Weight prep (4 weights, one launch): Wt[n][k] = fp16(W[k][n])
// ---------------------------------------------------------------------------
__global__ void wprep4_kernel(const float* __restrict__ W0,
                              const float* __restrict__ W1,
                              const float* __restrict__ W2,
                              const float* __restrict__ W3,
                              __half* __restrict__ base) {
    __shared__ float tile[32][33];
    const int which = blockIdx.x >> 6;
    const float* W = (which == 0) ? W0 : (which == 1) ? W1
                   : (which == 2) ? W2 : W3;
    __half* hi = base + (size_t)which * H * H;
    const int b  = blockIdx.x & 63;
    const int tx = threadIdx.x & 31;
    const int ty = threadIdx.x >> 5;
    const int bx = b & 7;
    const int by = b >> 3;
#pragma unroll
    for (int i = 0; i < 4; i++)
        tile[ty + i * 8][tx] = W[(by * 32 + ty + i * 8) * H + bx * 32 + tx];
    __syncthreads();
#pragma unroll
    for (int i = 0; i < 4; i++) {
        float v = tile[tx][ty + i * 8];
        int n = bx * 32 + ty + i * 8;
        int k = by * 32 + tx;
        hi[n * H + k] = __float2half_rn(v);
    }
}

// ---------------------------------------------------------------------------
// CSR build kernels
// ---------------------------------------------------------------------------
__global__ void zero2_kernel(int* __restrict__ a, int* __restrict__ b, int n) {
    int i = blockIdx.x * 256 + threadIdx.x;
    if (i < n) { a[i] = 0; b[i] = 0; }
}

__global__ void hist_kernel(const int* __restrict__ dst,
                            int* __restrict__ deg, int E) {
    int e = blockIdx.x * 256 + threadIdx.x;
    if (e < E) atomicAdd(&deg[__ldg(dst + e)], 1);
}

// --- 3-phase parallel exclusive scan (1024 elements per block) ---
__global__ void blocksum_kernel(const int* __restrict__ deg,
                                int* __restrict__ part, int n) {
    __shared__ int ws[8];
    int b = blockIdx.x, t = threadIdx.x;
    int base = b * 1024 + t * 4;
    int s = 0;
#pragma unroll
    for (int j = 0; j < 4; j++)
        if (base + j < n) s += __ldg(deg + base + j);
#pragma unroll
    for (int o = 16; o > 0; o >>= 1) s += __shfl_down_sync(~0u, s, o);
    if ((t & 31) == 0) ws[t >> 5] = s;
    __syncthreads();
    if (t == 0) {
        int tot = 0;
#pragma unroll
        for (int w = 0; w < 8; w++) tot += ws[w];
        part[b] = tot;
    }
}

__global__ void scanpart_kernel(int* __restrict__ part, int nblk,
                                int* __restrict__ off, int n) {
    __shared__ int sh[128];
    int t = threadIdx.x;
    int v = (t < nblk) ? part[t] : 0;
    sh[t] = v;
    __syncthreads();
    for (int o = 1; o < 128; o <<= 1) {
        int u = (t >= o) ? sh[t - o] : 0;
        __syncthreads();
        sh[t] += u;
        __syncthreads();
    }
    if (t < nblk) part[t] = sh[t] - v;   // exclusive
    if (t == 127) off[n] = sh[127];
}

__global__ void scan3_kernel(const int* __restrict__ deg,
                             const int* __restrict__ part,
                             int* __restrict__ off, int n) {
    __shared__ int ws[8];
    int b = blockIdx.x, t = threadIdx.x;
    int lane = t & 31, w = t >> 5;
    int base = b * 1024 + t * 4;
    int v[4];
#pragma unroll
    for (int j = 0; j < 4; j++)
        v[j] = (base + j < n) ? __ldg(deg + base + j) : 0;
    int s = v[0] + v[1] + v[2] + v[3];
    int ss = s;
#pragma unroll
    for (int o = 1; o < 32; o <<= 1) {
        int u = __shfl_up_sync(~0u, ss, o);
        if (lane >= o) ss += u;
    }
    if (lane == 31) ws[w] = ss;
    __syncthreads();
    if (w == 0 && lane < 8) {
        int x = ws[lane];
#pragma unroll
        for (int o = 1; o < 8; o <<= 1) {
            int u = __shfl_up_sync(0xFFu, x, o);
            if (lane >= o) x += u;
        }
        ws[lane] = x;
    }
    __syncthreads();
    int run = ss - s + (w > 0 ? ws[w - 1] : 0) + __ldg(part + b);
#pragma unroll
    for (int j = 0; j < 4; j++) {
        if (base + j < n) off[base + j] = run;
        run += v[j];
    }
}

__global__ void fill_kernel(const int* __restrict__ src,
                            const int* __restrict__ dst,
                            const float* __restrict__ ea,
                            const int* __restrict__ off,
                            int* __restrict__ cnt,
                            int* __restrict__ csrc,
                            float* __restrict__ cea, int E) {
    int e = blockIdx.x * 256 + threadIdx.x;
    if (e >= E) return;
    int d = __ldg(dst + e);
    int pos = __ldg(off + d) + atomicAdd(&cnt[d], 1);
    csrc[pos] = __ldg(src + e);
    cea[pos]  = __ldg(ea + e);
}

// ---------------------------------------------------------------------------
// Aggregate: agg[r] = sum_{edges->r} relu(x_src + ea*We + be). Warp per row.
// ---------------------------------------------------------------------------
__global__ void agg_kernel(const float* __restrict__ xsrc,
                           const int* __restrict__ off,
                           const int* __restrict__ csrc,
                           const float* __restrict__ cea,
                           const float* __restrict__ We,
                           const float* __restrict__ be,
                           float* __restrict__ agg, int M) {
    int r = blockIdx.x * 8 + (threadIdx.x >> 5);
    if (r >= M) return;
    int lane = threadIdx.x & 31;
    int col = lane * 8;

    float4 w0 = __ldg((const float4*)(We + col));
    float4 w1 = __ldg((const float4*)(We + col + 4));
    float4 b0 = __ldg((const float4*)(be + col));
    float4 b1 = __ldg((const float4*)(be + col + 4));

    float acc[8] = {0.f, 0.f, 0.f, 0.f, 0.f, 0.f, 0.f, 0.f};

    int i  = __ldg(off + r);
    int s1 = __ldg(off + r + 1);

    int   sn = 0;
    float an = 0.f;
    if (i < s1) { sn = __ldg(csrc + i); an = __ldg(cea + i); }

    while (i < s1) {
        int s = sn; float a = an;
        i++;
        if (i < s1) { sn = __ldg(csrc + i); an = __ldg(cea + i); }

        const float4* xp = (const float4*)(xsrc + (size_t)s * H + col);
        float4 x0 = xp[0], x1 = xp[1];
        acc[0] += fmaxf(x0.x + fmaf(a, w0.x, b0.x), 0.f);
        acc[1] += fmaxf(x0.y + fmaf(a, w0.y, b0.y), 0.f);
        acc[2] += fmaxf(x0.z + fmaf(a, w0.z, b0.z), 0.f);
        acc[3] += fmaxf(x0.w + fmaf(a, w0.w, b0.w), 0.f);
        acc[4] += fmaxf(x1.x + fmaf(a, w1.x, b1.x), 0.f);
        acc[5] += fmaxf(x1.y + fmaf(a, w1.y, b1.y), 0.f);
        acc[6] += fmaxf(x1.z + fmaf(a, w1.z, b1.z), 0.f);
        acc[7] += fmaxf(x1.w + fmaf(a, w1.w, b1.w), 0.f);
    }

    float* o = agg + (size_t)r * H + col;
    *(float4*)(o)     = make_float4(acc[0], acc[1], acc[2], acc[3]);
    *(float4*)(o + 4) = make_float4(acc[4], acc[5], acc[6], acc[7]);
}

// ---------------------------------------------------------------------------
// Fused GINE MLP: out = LN( relu((x+agg)@Wa + ba) @ Wb + bb + x ) * g + beta
// Pure fp16 single-pass MMA. Tile 64M x 256N, BK=32, 8 warps, 2 CTAs/SM.
// ---------------------------------------------------------------------------
__global__ __launch_bounds__(256, 2) void fused_gine(
    const float* __restrict__ X, const float* __restrict__ AGG,
    const __half* __restrict__ Wa, const __half* __restrict__ Wb,
    const float* __restrict__ ba, const float* __restrict__ bb,
    const float* __restrict__ gln, const float* __restrict__ bln,
    float* __restrict__ C, int M)
{
    extern __shared__ char sm[];
    const uint32_t sb = smem_u32(sm);

    const int t = threadIdx.x;
    const int lane = t & 31;
    const int wid = t >> 5;
    const int wm = wid & 1;
    const int wn = wid >> 1;
    const int bm = blockIdx.x * 64;

    float* b1S  = (float*)(sm + SM_B1);
    float* b2S  = (float*)(sm + SM_B2);
    float* gS   = (float*)(sm + SM_G);
    float* bS   = (float*)(sm + SM_BETA);
    float* psum = (float*)(sm + SM_PSUM);
    float* psq  = (float*)(sm + SM_PSQ);

    b1S[t] = ba[t];
    b2S[t] = bb[t];
    gS[t]  = gln[t];
    bS[t]  = bln[t];
    if (t < 64) { psum[t] = 0.f; psq[t] = 0.f; }

    float c[2][8][4];
#pragma unroll
    for (int i = 0; i < 2; i++)
#pragma unroll
        for (int j = 0; j < 8; j++)
#pragma unroll
            for (int e = 0; e < 4; e++) c[i][j][e] = 0.f;

    const int row_a = t >> 2;
    const int kq_a  = t & 3;
    const int grow_a = bm + row_a;
    const bool aval = (grow_a < M);

    auto lda = [&](int ck, float4& v0, float4& v1) {
        if (aval) {
            size_t off = (size_t)grow_a * H + ck * 32 + kq_a * 8;
            const float4* p = (const float4*)(X + off);
            const float4* q = (const float4*)(AGG + off);
            float4 a0 = p[0], a1 = p[1];
            float4 u0 = q[0], u1 = q[1];
            v0.x = a0.x + u0.x; v0.y = a0.y + u0.y;
            v0.z = a0.z + u0.z; v0.w = a0.w + u0.w;
            v1.x = a1.x + u1.x; v1.y = a1.y + u1.y;
            v1.z = a1.z + u1.z; v1.w = a1.w + u1.w;
        } else {
            v0 = make_float4(0.f, 0.f, 0.f, 0.f);
            v1 = v0;
        }
    };
    auto sts_a = [&](int st, float4 v0, float4 v1) {
        uint32_t hv[4];
        hv[0] = pack2h(v0.x, v0.y);
        hv[1] = pack2h(v0.z, v0.w);
        hv[2] = pack2h(v1.x, v1.y);
        hv[3] = pack2h(v1.z, v1.w);
        uint32_t o = (uint32_t)(row_a * 80 + kq_a * 16);
        *(uint4*)(sm + SM_A(st) + o) = make_uint4(hv[0], hv[1], hv[2], hv[3]);
    };
    auto cpw = [&](const __half* W, int ck, int st) {
        const __half* s = W + (size_t)t * H + ck * 32;
        uint32_t d = sb + SM_W(st) + t * 80;
#pragma unroll
        for (int q = 0; q < 4; q++) cp16(d + q * 16, s + q * 8);
    };

    const uint32_t a_off = (uint32_t)((lane & 15) * 80 + (lane >> 4) * 16);
    const uint32_t w_off = (uint32_t)((wn * 64 + (lane & 7) + ((lane >> 4) * 8)) * 80
                                      + (((lane >> 3) & 1) * 16));

    auto compute = [&](uint32_t aBase, uint32_t wBase) {
        const uint32_t ah_base = aBase + (uint32_t)(wm * 2560) + a_off;
        const uint32_t wh_base = wBase + w_off;
#pragma unroll
        for (int ks = 0; ks < 2; ks++) {
            uint32_t ah0[4], ah1[4];
            uint32_t ab = ah_base + ks * 32;
            ldsm_x4(ah0, ab);
            ldsm_x4(ah1, ab + 1280);
            uint32_t bf[4][4];
            uint32_t wb = wh_base + ks * 32;
#pragma unroll
            for (int n4 = 0; n4 < 4; n4++) ldsm_x4(bf[n4], wb + n4 * 1280);
#pragma unroll
            for (int n4 = 0; n4 < 4; n4++) {
                const int nf = n4 * 2;
                mma_f16(c[0][nf],     ah0, bf[n4][0], bf[n4][1]);
                mma_f16(c[0][nf + 1], ah0, bf[n4][2], bf[n4][3]);
                mma_f16(c[1][nf],     ah1, bf[n4][0], bf[n4][1]);
                mma_f16(c[1][nf + 1], ah1, bf[n4][2], bf[n4][3]);
            }
        }
    };

    const int qrow = lane >> 2;
    const int qcol = lane & 3;

    // =================== Phase A: acc1 = (X+AGG) @ Wa ===================
    float4 p0, p1, n0, n1;
    lda(0, p0, p1);
    cpw(Wa, 0, 0);
    CP_COMMIT();

#pragma unroll 1
    for (int ck = 0; ck < 8; ck++) {
        const int st = ck & 1;
        sts_a(st, p0, p1);
        if (ck < 7) {
            lda(ck + 1, n0, n1);
            cpw(Wa, ck + 1, st ^ 1);
            CP_COMMIT();
            CP_WAIT1();
        } else {
            CP_WAIT0();
        }
        __syncthreads();
        compute(sb + SM_A(st), sb + SM_W(st));
        __syncthreads();
        p0 = n0; p1 = n1;
    }

    // ---- epilogue 1: h = relu(acc1 + ba) -> smem fp16 (A layout) ----
#pragma unroll
    for (int mf = 0; mf < 2; mf++)
#pragma unroll
        for (int rh = 0; rh < 2; rh++) {
            int r = wm * 32 + mf * 16 + rh * 8 + qrow;
#pragma unroll
            for (int nf = 0; nf < 8; nf++) {
                int kcol = wn * 64 + nf * 8 + qcol * 2;
                float z0 = fmaxf(c[mf][nf][rh * 2]     + b1S[kcol],     0.f);
                float z1 = fmaxf(c[mf][nf][rh * 2 + 1] + b1S[kcol + 1], 0.f);
                uint32_t off = (uint32_t)((kcol >> 5) * 5120 + r * 80
                                          + (kcol & 31) * 2);
                *(uint32_t*)(sm + SM_H + off) = pack2h(z0, z1);
            }
        }

#pragma unroll
    for (int i = 0; i < 2; i++)
#pragma unroll
        for (int j = 0; j < 8; j++)
#pragma unroll
            for (int e = 0; e < 4; e++) c[i][j][e] = 0.f;

    // =================== Phase B: acc2 = h @ Wb =========================
    cpw(Wb, 0, 0);
    CP_COMMIT();

#pragma unroll 1
    for (int ck = 0; ck < 8; ck++) {
        const int st = ck & 1;
        if (ck < 7) {
            cpw(Wb, ck + 1, st ^ 1);
            CP_COMMIT();
            CP_WAIT1();
        } else {
            CP_WAIT0();
        }
        __syncthreads();
        compute(sb + SM_H + ck * 5120, sb + SM_W(st));
        __syncthreads();
    }

    // ---- epilogue 2: LN(acc2 + bb + X) * g + beta ----
#pragma unroll
    for (int mf = 0; mf < 2; mf++)
#pragma unroll
        for (int rh = 0; rh < 2; rh++) {
            int r = wm * 32 + mf * 16 + rh * 8 + qrow;
            int grow = bm + r;
            float su = 0.f, sq = 0.f;
            if (grow < M) {
                const float* rrow = X + (size_t)grow * H;
#pragma unroll
                for (int nf = 0; nf < 8; nf++) {
                    int col = wn * 64 + nf * 8 + qcol * 2;
                    float2 rv = *(const float2*)(rrow + col);
                    float z0 = c[mf][nf][rh * 2]     + b2S[col]     + rv.x;
                    float z1 = c[mf][nf][rh * 2 + 1] + b2S[col + 1] + rv.y;
                    c[mf][nf][rh * 2]     = z0;
                    c[mf][nf][rh * 2 + 1] = z1;
                    su += z0 + z1;
                    sq += z0 * z0 + z1 * z1;
                }
            }
            su += __shfl_xor_sync(0xFFFFFFFFu, su, 1);
            su += __shfl_xor_sync(0xFFFFFFFFu, su, 2);
            sq += __shfl_xor_sync(0xFFFFFFFFu, sq, 1);
            sq += __shfl_xor_sync(0xFFFFFFFFu, sq, 2);
            if (qcol == 0 && grow < M) {
                atomicAdd(&psum[r], su);
                atomicAdd(&psq[r], sq);
            }
        }
    __syncthreads();
#pragma unroll
    for (int mf = 0; mf < 2; mf++)
#pragma unroll
        for (int rh = 0; rh < 2; rh++) {
            int r = wm * 32 + mf * 16 + rh * 8 + qrow;
            int grow = bm + r;
            if (grow >= M) continue;
            float mu = psum[r] * (1.f / 256.f);
            float var = psq[r] * (1.f / 256.f) - mu * mu;
            float rs = rsqrtf(var + LN_EPS);
            float* crow = C + (size_t)grow * H;
#pragma unroll
            for (int nf = 0; nf < 8; nf++) {
                int col = wn * 64 + nf * 8 + qcol * 2;
                float2 o;
                o.x = (c[mf][nf][rh * 2]     - mu) * rs * gS[col]     + bS[col];
                o.y = (c[mf][nf][rh * 2 + 1] - mu) * rs * gS[col + 1] + bS[col + 1];
                *(float2*)(crow + col) = o;
            }
        }
}

// ---------------------------------------------------------------------------
// launch
// ---------------------------------------------------------------------------
extern "C" void kernel_launch(void* const* d_in, const int* in_sizes, int n_in,
                              void* d_out, int out_size) {
    const float* x_var    = (const float*)d_in[0];
    const float* x_constr = (const float*)d_in[1];
    const int*   ei_v2c   = (const int*)  d_in[2];
    const int*   ei_c2v   = (const int*)  d_in[3];
    const float* ea       = (const float*)d_in[4];
    const float* We1 = (const float*)d_in[5];
    const float* be1 = (const float*)d_in[6];
    const float* W1a = (const float*)d_in[7];
    const float* b1a = (const float*)d_in[8];
    const float* W1b = (const float*)d_in[9];
    const float* b1b = (const float*)d_in[10];
    const float* We2 = (const float*)d_in[11];
    const float* be2 = (const float*)d_in[12];
    const float* W2a = (const float*)d_in[13];
    const float* b2a = (const float*)d_in[14];
    const float* W2b = (const float*)d_in[15];
    const float* b2b = (const float*)d_in[16];
    const float* g_constr    = (const float*)d_in[17];
    const float* beta_constr = (const float*)d_in[18];
    const float* g_var       = (const float*)d_in[19];
    const float* beta_var    = (const float*)d_in[20];

    const int NVr = in_sizes[0] / H;
    const int NCr = in_sizes[1] / H;
    const int Ecnt = in_sizes[4];

    float* agg;
    cudaGetSymbolAddress((void**)&agg, g_agg);
    __half* wt;
    cudaGetSymbolAddress((void**)&wt, g_wt);
    int *deg, *cnt, *off, *part, *csrc;
    float *cea;
    cudaGetSymbolAddress((void**)&deg, g_deg);
    cudaGetSymbolAddress((void**)&cnt, g_cnt);
    cudaGetSymbolAddress((void**)&off, g_off);
    cudaGetSymbolAddress((void**)&part, g_part);
    cudaGetSymbolAddress((void**)&csrc, g_csrc);
    cudaGetSymbolAddress((void**)&cea, g_cea);

    __half* wt1a = wt;
    __half* wt1b = wt + H * H;
    __half* wt2a = wt + 2 * H * H;
    __half* wt2b = wt + 3 * H * H;

    cudaFuncSetAttribute(fused_gine,
                         cudaFuncAttributeMaxDynamicSharedMemorySize, SMEM_T);

    float* out_var    = (float*)d_out;
    float* out_constr = (float*)d_out + (size_t)NVr * H;

    const int eb = (Ecnt + 255) / 256;

    wprep4_kernel<<<256, 256>>>(W1a, W1b, W2a, W2b, wt);

    // ---- stage 1: var -> constr ----
    {
        const int* src1 = ei_v2c;
        const int* dst1 = ei_v2c + Ecnt;
        int nblk = (NCr + 1023) / 1024;
        zero2_kernel<<<(NCr + 255) / 256, 256>>>(deg, cnt, NCr);
        hist_kernel<<<eb, 256>>>(dst1, deg, Ecnt);
        blocksum_kernel<<<nblk, 256>>>(deg, part, NCr);
        scanpart_kernel<<<1, 128>>>(part, nblk, off, NCr);
        scan3_kernel<<<nblk, 256>>>(deg, part, off, NCr);
        fill_kernel<<<eb, 256>>>(src1, dst1, ea, off, cnt, csrc, cea, Ecnt);
        agg_kernel<<<(NCr + 7) / 8, 256>>>(x_var, off, csrc, cea,
                                           We1, be1, agg, NCr);
        int gx = (NCr + 63) / 64;
        fused_gine<<<gx, 256, SMEM_T>>>(
            x_constr, agg, wt1a, wt1b, b1a, b1b,
            g_constr, beta_constr, out_constr, NCr);
    }

    // ---- stage 2: constr -> var (reads LN'd x_constr from d_out) ----
    {
        const int* src2 = ei_c2v;
        const int* dst2 = ei_c2v + Ecnt;
        int nblk = (NVr + 1023) / 1024;
        zero2_kernel<<<(NVr + 255) / 256, 256>>>(deg, cnt, NVr);
        hist_kernel<<<eb, 256>>>(dst2, deg, Ecnt);
        blocksum_kernel<<<nblk, 256>>>(deg, part, NVr);
        scanpart_kernel<<<1, 128>>>(part, nblk, off, NVr);
        scan3_kernel<<<nblk, 256>>>(deg, part, off, NVr);
        fill_kernel<<<eb, 256>>>(src2, dst2, ea, off, cnt, csrc, cea, Ecnt);
        agg_kernel<<<(NVr + 7) / 8, 256>>>(out_constr, off, csrc, cea,
                                           We2, be2, agg, NVr);
        int gx = (NVr + 63) / 64;
        fused_gine<<<gx, 256, SMEM_T>>>(
            x_var, agg, wt2a, wt2b, b2a, b2b,
            g_var, beta_var, out_var, NVr);
    }
}

// round 12
// speedup vs baseline: 1.2216x; 1.0170x over previous
#include <cuda_runtime.h>
#include <cuda_fp16.h>
#include <cstdint>

#define H 256
#define MAXROWS 50000
#define NMAX 50048
#define EMAX 300000
#define LN_EPS 1e-5f

// ---------------------------------------------------------------------------
// Scratch (__device__ globals: allocation-free rule)
// ---------------------------------------------------------------------------
__device__ uint32_t g_axh[NMAX * (H / 2)];   // fp16x2 packed (x_dst + agg)
__device__ __half g_wt[4][H * H];            // transposed fp16 weights
__device__ int   g_deg[NMAX];
__device__ int   g_cnt[NMAX];
__device__ int   g_off[NMAX + 1];
__device__ int   g_part[64];
__device__ int   g_csrc[EMAX];
__device__ float g_cea[EMAX];

// ---------------------------------------------------------------------------
// PTX helpers
// ---------------------------------------------------------------------------
__device__ __forceinline__ uint32_t smem_u32(const void* p) {
    uint32_t a;
    asm("{ .reg .u64 t; cvta.to.shared.u64 t, %1; cvt.u32.u64 %0, t; }"
        : "=r"(a) : "l"(p));
    return a;
}
__device__ __forceinline__ void ldsm_x4(uint32_t r[4], uint32_t addr) {
    asm volatile("ldmatrix.sync.aligned.m8n8.x4.shared.b16 {%0,%1,%2,%3}, [%4];"
                 : "=r"(r[0]), "=r"(r[1]), "=r"(r[2]), "=r"(r[3]) : "r"(addr));
}
__device__ __forceinline__ void mma_f16(float c[4],
                                        const uint32_t a[4],
                                        uint32_t b0, uint32_t b1) {
    asm volatile(
        "mma.sync.aligned.m16n8k16.row.col.f32.f16.f16.f32 "
        "{%0,%1,%2,%3}, {%4,%5,%6,%7}, {%8,%9}, {%0,%1,%2,%3};"
        : "+f"(c[0]), "+f"(c[1]), "+f"(c[2]), "+f"(c[3])
        : "r"(a[0]), "r"(a[1]), "r"(a[2]), "r"(a[3]), "r"(b0), "r"(b1));
}
__device__ __forceinline__ void cp16(uint32_t dst, const void* src) {
    asm volatile("cp.async.ca.shared.global [%0], [%1], 16;"
                 :: "r"(dst), "l"(src) : "memory");
}
#define CP_COMMIT() asm volatile("cp.async.commit_group;" ::: "memory")
#define CP_WAIT1()  asm volatile("cp.async.wait_group 1;" ::: "memory")
#define CP_WAIT0()  asm volatile("cp.async.wait_group 0;" ::: "memory")

__device__ __forceinline__ uint32_t pack2h(float a, float b) {
    __half2 h = __floats2half2_rn(a, b);
    return *(uint32_t*)&h;
}

// ---------------------------------------------------------------------------
// SMEM layout for fused_gine (bytes)
// ---------------------------------------------------------------------------
#define SM_A(st)   ((st) * 5120)
#define SM_W(st)   (10240 + (st) * 20480)
#define SM_H       51200
#define SM_B1      92160
#define SM_B2      93184
#define SM_G       94208
#define SM_BETA    95232
#define SM_PSUM    96256
#define SM_PSQ     96512
#define SMEM_T     96768

// ---------------------------------------------------------------------------
// Weight prep (4 weights, one launch): Wt[n][k] = fp16(W[k][n])
// ---------------------------------------------------------------------------
__global__ void wprep4_kernel(const float* __restrict__ W0,
                              const float* __restrict__ W1,
                              const float* __restrict__ W2,
                              const float* __restrict__ W3,
                              __half* __restrict__ base) {
    __shared__ float tile[32][33];
    const int which = blockIdx.x >> 6;
    const float* W = (which == 0) ? W0 : (which == 1) ? W1
                   : (which == 2) ? W2 : W3;
    __half* hi = base + (size_t)which * H * H;
    const int b  = blockIdx.x & 63;
    const int tx = threadIdx.x & 31;
    const int ty = threadIdx.x >> 5;
    const int bx = b & 7;
    const int by = b >> 3;
#pragma unroll
    for (int i = 0; i < 4; i++)
        tile[ty + i * 8][tx] = W[(by * 32 + ty + i * 8) * H + bx * 32 + tx];
    __syncthreads();
#pragma unroll
    for (int i = 0; i < 4; i++) {
        float v = tile[tx][ty + i * 8];
        int n = bx * 32 + ty + i * 8;
        int k = by * 32 + tx;
        hi[n * H + k] = __float2half_rn(v);
    }
}

// ---------------------------------------------------------------------------
// CSR build kernels
// ---------------------------------------------------------------------------
__global__ void zero2_kernel(int* __restrict__ a, int* __restrict__ b, int n) {
    int i = blockIdx.x * 256 + threadIdx.x;
    if (i < n) { a[i] = 0; b[i] = 0; }
}

__global__ void hist_kernel(const int* __restrict__ dst,
                            int* __restrict__ deg, int E) {
    int e = blockIdx.x * 256 + threadIdx.x;
    if (e < E) atomicAdd(&deg[__ldg(dst + e)], 1);
}

__global__ void blocksum_kernel(const int* __restrict__ deg,
                                int* __restrict__ part, int n) {
    __shared__ int ws[8];
    int b = blockIdx.x, t = threadIdx.x;
    int base = b * 1024 + t * 4;
    int s = 0;
#pragma unroll
    for (int j = 0; j < 4; j++)
        if (base + j < n) s += __ldg(deg + base + j);
#pragma unroll
    for (int o = 16; o > 0; o >>= 1) s += __shfl_down_sync(~0u, s, o);
    if ((t & 31) == 0) ws[t >> 5] = s;
    __syncthreads();
    if (t == 0) {
        int tot = 0;
#pragma unroll
        for (int w = 0; w < 8; w++) tot += ws[w];
        part[b] = tot;
    }
}

__global__ void scanpart_kernel(int* __restrict__ part, int nblk,
                                int* __restrict__ off, int n) {
    __shared__ int sh[128];
    int t = threadIdx.x;
    int v = (t < nblk) ? part[t] : 0;
    sh[t] = v;
    __syncthreads();
    for (int o = 1; o < 128; o <<= 1) {
        int u = (t >= o) ? sh[t - o] : 0;
        __syncthreads();
        sh[t] += u;
        __syncthreads();
    }
    if (t < nblk) part[t] = sh[t] - v;   // exclusive
    if (t == 127) off[n] = sh[127];
}

__global__ void scan3_kernel(const int* __restrict__ deg,
                             const int* __restrict__ part,
                             int* __restrict__ off, int n) {
    __shared__ int ws[8];
    int b = blockIdx.x, t = threadIdx.x;
    int lane = t & 31, w = t >> 5;
    int base = b * 1024 + t * 4;
    int v[4];
#pragma unroll
    for (int j = 0; j < 4; j++)
        v[j] = (base + j < n) ? __ldg(deg + base + j) : 0;
    int s = v[0] + v[1] + v[2] + v[3];
    int ss = s;
#pragma unroll
    for (int o = 1; o < 32; o <<= 1) {
        int u = __shfl_up_sync(~0u, ss, o);
        if (lane >= o) ss += u;
    }
    if (lane == 31) ws[w] = ss;
    __syncthreads();
    if (w == 0 && lane < 8) {
        int x = ws[lane];
#pragma unroll
        for (int o = 1; o < 8; o <<= 1) {
            int u = __shfl_up_sync(0xFFu, x, o);
            if (lane >= o) x += u;
        }
        ws[lane] = x;
    }
    __syncthreads();
    int run = ss - s + (w > 0 ? ws[w - 1] : 0) + __ldg(part + b);
#pragma unroll
    for (int j = 0; j < 4; j++) {
        if (base + j < n) off[base + j] = run;
        run += v[j];
    }
}

__global__ void fill_kernel(const int* __restrict__ src,
                            const int* __restrict__ dst,
                            const float* __restrict__ ea,
                            const int* __restrict__ off,
                            int* __restrict__ cnt,
                            int* __restrict__ csrc,
                            float* __restrict__ cea, int E) {
    int e = blockIdx.x * 256 + threadIdx.x;
    if (e >= E) return;
    int d = __ldg(dst + e);
    int pos = __ldg(off + d) + atomicAdd(&cnt[d], 1);
    csrc[pos] = __ldg(src + e);
    cea[pos]  = __ldg(ea + e);
}

// ---------------------------------------------------------------------------
// Aggregate + pack: axh[r] = fp16( x_dst[r] + sum_{edges->r} relu(x_src + ea*We + be) )
// Warp per row; fp32 accumulation; emits packed fp16x2.
// ---------------------------------------------------------------------------
__global__ void agg_kernel(const float* __restrict__ xsrc,
                           const float* __restrict__ xdst,
                           const int* __restrict__ off,
                           const int* __restrict__ csrc,
                           const float* __restrict__ cea,
                           const float* __restrict__ We,
                           const float* __restrict__ be,
                           uint32_t* __restrict__ axh, int M) {
    int r = blockIdx.x * 8 + (threadIdx.x >> 5);
    if (r >= M) return;
    int lane = threadIdx.x & 31;
    int col = lane * 8;

    float4 w0 = __ldg((const float4*)(We + col));
    float4 w1 = __ldg((const float4*)(We + col + 4));
    float4 b0 = __ldg((const float4*)(be + col));
    float4 b1 = __ldg((const float4*)(be + col + 4));

    const float4* dp = (const float4*)(xdst + (size_t)r * H + col);
    float4 d0 = dp[0], d1 = dp[1];
    float acc[8] = {d0.x, d0.y, d0.z, d0.w, d1.x, d1.y, d1.z, d1.w};

    int i  = __ldg(off + r);
    int s1 = __ldg(off + r + 1);

    int   sn = 0;
    float an = 0.f;
    if (i < s1) { sn = __ldg(csrc + i); an = __ldg(cea + i); }

    while (i < s1) {
        int s = sn; float a = an;
        i++;
        if (i < s1) { sn = __ldg(csrc + i); an = __ldg(cea + i); }

        const float4* xp = (const float4*)(xsrc + (size_t)s * H + col);
        float4 x0 = xp[0], x1 = xp[1];
        acc[0] += fmaxf(x0.x + fmaf(a, w0.x, b0.x), 0.f);
        acc[1] += fmaxf(x0.y + fmaf(a, w0.y, b0.y), 0.f);
        acc[2] += fmaxf(x0.z + fmaf(a, w0.z, b0.z), 0.f);
        acc[3] += fmaxf(x0.w + fmaf(a, w0.w, b0.w), 0.f);
        acc[4] += fmaxf(x1.x + fmaf(a, w1.x, b1.x), 0.f);
        acc[5] += fmaxf(x1.y + fmaf(a, w1.y, b1.y), 0.f);
        acc[6] += fmaxf(x1.z + fmaf(a, w1.z, b1.z), 0.f);
        acc[7] += fmaxf(x1.w + fmaf(a, w1.w, b1.w), 0.f);
    }

    uint4 o;
    o.x = pack2h(acc[0], acc[1]);
    o.y = pack2h(acc[2], acc[3]);
    o.z = pack2h(acc[4], acc[5]);
    o.w = pack2h(acc[6], acc[7]);
    *(uint4*)(axh + (size_t)r * (H / 2) + lane * 4) = o;
}

// ---------------------------------------------------------------------------
// Fused GINE MLP: out = LN( relu(axh@Wa + ba) @ Wb + bb + x ) * g + beta
// Pure fp16 single-pass MMA; A streamed from pre-packed fp16 planes.
// Tile 64M x 256N, BK=32, 8 warps, 2 CTAs/SM.
// ---------------------------------------------------------------------------
__global__ __launch_bounds__(256, 2) void fused_gine(
    const uint32_t* __restrict__ AXH, const float* __restrict__ X,
    const __half* __restrict__ Wa, const __half* __restrict__ Wb,
    const float* __restrict__ ba, const float* __restrict__ bb,
    const float* __restrict__ gln, const float* __restrict__ bln,
    float* __restrict__ C, int M)
{
    extern __shared__ char sm[];
    const uint32_t sb = smem_u32(sm);

    const int t = threadIdx.x;
    const int lane = t & 31;
    const int wid = t >> 5;
    const int wm = wid & 1;
    const int wn = wid >> 1;
    const int bm = blockIdx.x * 64;

    float* b1S  = (float*)(sm + SM_B1);
    float* b2S  = (float*)(sm + SM_B2);
    float* gS   = (float*)(sm + SM_G);
    float* bS   = (float*)(sm + SM_BETA);
    float* psum = (float*)(sm + SM_PSUM);
    float* psq  = (float*)(sm + SM_PSQ);

    b1S[t] = ba[t];
    b2S[t] = bb[t];
    gS[t]  = gln[t];
    bS[t]  = bln[t];
    if (t < 64) { psum[t] = 0.f; psq[t] = 0.f; }

    float c[2][8][4];
#pragma unroll
    for (int i = 0; i < 2; i++)
#pragma unroll
        for (int j = 0; j < 8; j++)
#pragma unroll
            for (int e = 0; e < 4; e++) c[i][j][e] = 0.f;

    // A chunk loader: pure cp.async from packed fp16 (x+agg) planes.
    auto cpa = [&](int ck, int st) {
        const char* s = (const char*)AXH
                      + ((size_t)(bm + (t >> 2)) * 512) + ck * 64 + (t & 3) * 16;
        cp16(sb + SM_A(st) + (uint32_t)((t >> 2) * 80 + (t & 3) * 16), s);
    };
    auto cpw = [&](const __half* W, int ck, int st) {
        const __half* s = W + (size_t)t * H + ck * 32;
        uint32_t d = sb + SM_W(st) + t * 80;
#pragma unroll
        for (int q = 0; q < 4; q++) cp16(d + q * 16, s + q * 8);
    };

    const uint32_t a_off = (uint32_t)((lane & 15) * 80 + (lane >> 4) * 16);
    const uint32_t w_off = (uint32_t)((wn * 64 + (lane & 7) + ((lane >> 4) * 8)) * 80
                                      + (((lane >> 3) & 1) * 16));

    auto compute = [&](uint32_t aBase, uint32_t wBase) {
        const uint32_t ah_base = aBase + (uint32_t)(wm * 2560) + a_off;
        const uint32_t wh_base = wBase + w_off;
#pragma unroll
        for (int ks = 0; ks < 2; ks++) {
            uint32_t ah0[4], ah1[4];
            uint32_t ab = ah_base + ks * 32;
            ldsm_x4(ah0, ab);
            ldsm_x4(ah1, ab + 1280);
            uint32_t bf[4][4];
            uint32_t wb = wh_base + ks * 32;
#pragma unroll
            for (int n4 = 0; n4 < 4; n4++) ldsm_x4(bf[n4], wb + n4 * 1280);
#pragma unroll
            for (int n4 = 0; n4 < 4; n4++) {
                const int nf = n4 * 2;
                mma_f16(c[0][nf],     ah0, bf[n4][0], bf[n4][1]);
                mma_f16(c[0][nf + 1], ah0, bf[n4][2], bf[n4][3]);
                mma_f16(c[1][nf],     ah1, bf[n4][0], bf[n4][1]);
                mma_f16(c[1][nf + 1], ah1, bf[n4][2], bf[n4][3]);
            }
        }
    };

    const int qrow = lane >> 2;
    const int qcol = lane & 3;

    // =================== Phase A: acc1 = AXH @ Wa ===================
    cpa(0, 0);
    cpw(Wa, 0, 0);
    CP_COMMIT();

#pragma unroll 1
    for (int ck = 0; ck < 8; ck++) {
        const int st = ck & 1;
        if (ck < 7) {
            cpa(ck + 1, st ^ 1);
            cpw(Wa, ck + 1, st ^ 1);
            CP_COMMIT();
            CP_WAIT1();
        } else {
            CP_WAIT0();
        }
        __syncthreads();
        compute(sb + SM_A(st), sb + SM_W(st));
        __syncthreads();
    }

    // ---- epilogue 1: h = relu(acc1 + ba) -> smem fp16 (A layout) ----
#pragma unroll
    for (int mf = 0; mf < 2; mf++)
#pragma unroll
        for (int rh = 0; rh < 2; rh++) {
            int r = wm * 32 + mf * 16 + rh * 8 + qrow;
#pragma unroll
            for (int nf = 0; nf < 8; nf++) {
                int kcol = wn * 64 + nf * 8 + qcol * 2;
                float z0 = fmaxf(c[mf][nf][rh * 2]     + b1S[kcol],     0.f);
                float z1 = fmaxf(c[mf][nf][rh * 2 + 1] + b1S[kcol + 1], 0.f);
                uint32_t off = (uint32_t)((kcol >> 5) * 5120 + r * 80
                                          + (kcol & 31) * 2);
                *(uint32_t*)(sm + SM_H + off) = pack2h(z0, z1);
            }
        }

#pragma unroll
    for (int i = 0; i < 2; i++)
#pragma unroll
        for (int j = 0; j < 8; j++)
#pragma unroll
            for (int e = 0; e < 4; e++) c[i][j][e] = 0.f;

    // =================== Phase B: acc2 = h @ Wb =========================
    cpw(Wb, 0, 0);
    CP_COMMIT();

#pragma unroll 1
    for (int ck = 0; ck < 8; ck++) {
        const int st = ck & 1;
        if (ck < 7) {
            cpw(Wb, ck + 1, st ^ 1);
            CP_COMMIT();
            CP_WAIT1();
        } else {
            CP_WAIT0();
        }
        __syncthreads();
        compute(sb + SM_H + ck * 5120, sb + SM_W(st));
        __syncthreads();
    }

    // ---- epilogue 2: LN(acc2 + bb + X) * g + beta ----
#pragma unroll
    for (int mf = 0; mf < 2; mf++)
#pragma unroll
        for (int rh = 0; rh < 2; rh++) {
            int r = wm * 32 + mf * 16 + rh * 8 + qrow;
            int grow = bm + r;
            float su = 0.f, sq = 0.f;
            if (grow < M) {
                const float* rrow = X + (size_t)grow * H;
#pragma unroll
                for (int nf = 0; nf < 8; nf++) {
                    int col = wn * 64 + nf * 8 + qcol * 2;
                    float2 rv = *(const float2*)(rrow + col);
                    float z0 = c[mf][nf][rh * 2]     + b2S[col]     + rv.x;
                    float z1 = c[mf][nf][rh * 2 + 1] + b2S[col + 1] + rv.y;
                    c[mf][nf][rh * 2]     = z0;
                    c[mf][nf][rh * 2 + 1] = z1;
                    su += z0 + z1;
                    sq += z0 * z0 + z1 * z1;
                }
            }
            su += __shfl_xor_sync(0xFFFFFFFFu, su, 1);
            su += __shfl_xor_sync(0xFFFFFFFFu, su, 2);
            sq += __shfl_xor_sync(0xFFFFFFFFu, sq, 1);
            sq += __shfl_xor_sync(0xFFFFFFFFu, sq, 2);
            if (qcol == 0 && grow < M) {
                atomicAdd(&psum[r], su);
                atomicAdd(&psq[r], sq);
            }
        }
    __syncthreads();
#pragma unroll
    for (int mf = 0; mf < 2; mf++)
#pragma unroll
        for (int rh = 0; rh < 2; rh++) {
            int r = wm * 32 + mf * 16 + rh * 8 + qrow;
            int grow = bm + r;
            if (grow >= M) continue;
            float mu = psum[r] * (1.f / 256.f);
            float var = psq[r] * (1.f / 256.f) - mu * mu;
            float rs = rsqrtf(var + LN_EPS);
            float* crow = C + (size_t)grow * H;
#pragma unroll
            for (int nf = 0; nf < 8; nf++) {
                int col = wn * 64 + nf * 8 + qcol * 2;
                float2 o;
                o.x = (c[mf][nf][rh * 2]     - mu) * rs * gS[col]     + bS[col];
                o.y = (c[mf][nf][rh * 2 + 1] - mu) * rs * gS[col + 1] + bS[col + 1];
                *(float2*)(crow + col) = o;
            }
        }
}

// ---------------------------------------------------------------------------
// launch
// ---------------------------------------------------------------------------
extern "C" void kernel_launch(void* const* d_in, const int* in_sizes, int n_in,
                              void* d_out, int out_size) {
    const float* x_var    = (const float*)d_in[0];
    const float* x_constr = (const float*)d_in[1];
    const int*   ei_v2c   = (const int*)  d_in[2];
    const int*   ei_c2v   = (const int*)  d_in[3];
    const float* ea       = (const float*)d_in[4];
    const float* We1 = (const float*)d_in[5];
    const float* be1 = (const float*)d_in[6];
    const float* W1a = (const float*)d_in[7];
    const float* b1a = (const float*)d_in[8];
    const float* W1b = (const float*)d_in[9];
    const float* b1b = (const float*)d_in[10];
    const float* We2 = (const float*)d_in[11];
    const float* be2 = (const float*)d_in[12];
    const float* W2a = (const float*)d_in[13];
    const float* b2a = (const float*)d_in[14];
    const float* W2b = (const float*)d_in[15];
    const float* b2b = (const float*)d_in[16];
    const float* g_constr    = (const float*)d_in[17];
    const float* beta_constr = (const float*)d_in[18];
    const float* g_var       = (const float*)d_in[19];
    const float* beta_var    = (const float*)d_in[20];

    const int NVr = in_sizes[0] / H;
    const int NCr = in_sizes[1] / H;
    const int Ecnt = in_sizes[4];

    uint32_t* axh;
    cudaGetSymbolAddress((void**)&axh, g_axh);
    __half* wt;
    cudaGetSymbolAddress((void**)&wt, g_wt);
    int *deg, *cnt, *off, *part, *csrc;
    float *cea;
    cudaGetSymbolAddress((void**)&deg, g_deg);
    cudaGetSymbolAddress((void**)&cnt, g_cnt);
    cudaGetSymbolAddress((void**)&off, g_off);
    cudaGetSymbolAddress((void**)&part, g_part);
    cudaGetSymbolAddress((void**)&csrc, g_csrc);
    cudaGetSymbolAddress((void**)&cea, g_cea);

    __half* wt1a = wt;
    __half* wt1b = wt + H * H;
    __half* wt2a = wt + 2 * H * H;
    __half* wt2b = wt + 3 * H * H;

    cudaFuncSetAttribute(fused_gine,
                         cudaFuncAttributeMaxDynamicSharedMemorySize, SMEM_T);

    float* out_var    = (float*)d_out;
    float* out_constr = (float*)d_out + (size_t)NVr * H;

    const int eb = (Ecnt + 255) / 256;

    wprep4_kernel<<<256, 256>>>(W1a, W1b, W2a, W2b, wt);

    // ---- stage 1: var -> constr ----
    {
        const int* src1 = ei_v2c;
        const int* dst1 = ei_v2c + Ecnt;
        int nblk = (NCr + 1023) / 1024;
        zero2_kernel<<<(NCr + 255) / 256, 256>>>(deg, cnt, NCr);
        hist_kernel<<<eb, 256>>>(dst1, deg, Ecnt);
        blocksum_kernel<<<nblk, 256>>>(deg, part, NCr);
        scanpart_kernel<<<1, 128>>>(part, nblk, off, NCr);
        scan3_kernel<<<nblk, 256>>>(deg, part, off, NCr);
        fill_kernel<<<eb, 256>>>(src1, dst1, ea, off, cnt, csrc, cea, Ecnt);
        agg_kernel<<<(NCr + 7) / 8, 256>>>(x_var, x_constr, off, csrc, cea,
                                           We1, be1, axh, NCr);
        int gx = (NCr + 63) / 64;
        fused_gine<<<gx, 256, SMEM_T>>>(
            axh, x_constr, wt1a, wt1b, b1a, b1b,
            g_constr, beta_constr, out_constr, NCr);
    }

    // ---- stage 2: constr -> var (reads LN'd x_constr from d_out) ----
    {
        const int* src2 = ei_c2v;
        const int* dst2 = ei_c2v + Ecnt;
        int nblk = (NVr + 1023) / 1024;
        zero2_kernel<<<(NVr + 255) / 256, 256>>>(deg, cnt, NVr);
        hist_kernel<<<eb, 256>>>(dst2, deg, Ecnt);
        blocksum_kernel<<<nblk, 256>>>(deg, part, NVr);
        scanpart_kernel<<<1, 128>>>(part, nblk, off, NVr);
        scan3_kernel<<<nblk, 256>>>(deg, part, off, NVr);
        fill_kernel<<<eb, 256>>>(src2, dst2, ea, off, cnt, csrc, cea, Ecnt);
        agg_kernel<<<(NVr + 7) / 8, 256>>>(out_constr, x_var, off, csrc, cea,
                                           We2, be2, axh, NVr);
        int gx = (NVr + 63) / 64;
        fused_gine<<<gx, 256, SMEM_T>>>(
            axh, x_var, wt2a, wt2b, b2a, b2b,
            g_var, beta_var, out_var, NVr);
    }
}

// round 13
// speedup vs baseline: 1.4240x; 1.1656x over previous
#include <cuda_runtime.h>
#include <cuda_fp16.h>
#include <cstdint>

#define H 256
#define MAXROWS 50000
#define NMAX 50048
#define EMAX 300000
#define LN_EPS 1e-5f

// ---------------------------------------------------------------------------
// Scratch (__device__ globals: allocation-free rule)
// ---------------------------------------------------------------------------
__device__ uint32_t g_axh[NMAX * (H / 2)];   // fp16x2 packed (x_dst + agg)
__device__ __half g_wt[4][H * H];            // transposed fp16 weights
__device__ int   g_deg[NMAX];
__device__ int   g_cnt[NMAX];
__device__ int   g_off[NMAX + 1];
__device__ int   g_part[64];
__device__ int   g_csrc[EMAX];
__device__ float g_cea[EMAX];

// ---------------------------------------------------------------------------
// PTX helpers
// ---------------------------------------------------------------------------
__device__ __forceinline__ uint32_t smem_u32(const void* p) {
    uint32_t a;
    asm("{ .reg .u64 t; cvta.to.shared.u64 t, %1; cvt.u32.u64 %0, t; }"
        : "=r"(a) : "l"(p));
    return a;
}
__device__ __forceinline__ void ldsm_x4(uint32_t r[4], uint32_t addr) {
    asm volatile("ldmatrix.sync.aligned.m8n8.x4.shared.b16 {%0,%1,%2,%3}, [%4];"
                 : "=r"(r[0]), "=r"(r[1]), "=r"(r[2]), "=r"(r[3]) : "r"(addr));
}
__device__ __forceinline__ void mma_f16(float c[4],
                                        const uint32_t a[4],
                                        uint32_t b0, uint32_t b1) {
    asm volatile(
        "mma.sync.aligned.m16n8k16.row.col.f32.f16.f16.f32 "
        "{%0,%1,%2,%3}, {%4,%5,%6,%7}, {%8,%9}, {%0,%1,%2,%3};"
        : "+f"(c[0]), "+f"(c[1]), "+f"(c[2]), "+f"(c[3])
        : "r"(a[0]), "r"(a[1]), "r"(a[2]), "r"(a[3]), "r"(b0), "r"(b1));
}
__device__ __forceinline__ void cp16(uint32_t dst, const void* src) {
    asm volatile("cp.async.ca.shared.global [%0], [%1], 16;"
                 :: "r"(dst), "l"(src) : "memory");
}
#define CP_COMMIT() asm volatile("cp.async.commit_group;" ::: "memory")
#define CP_WAIT1()  asm volatile("cp.async.wait_group 1;" ::: "memory")
#define CP_WAIT0()  asm volatile("cp.async.wait_group 0;" ::: "memory")

__device__ __forceinline__ uint32_t pack2h(float a, float b) {
    __half2 h = __floats2half2_rn(a, b);
    return *(uint32_t*)&h;
}

// ---------------------------------------------------------------------------
// SMEM layout for fused_gine (bytes). M-tile = 128 rows.
//   A chunk: [128 rows][40 fp16] (80B stride), 2 stages.
//   W chunk: [256 n][40 fp16], 2 stages.
//   h: 8 chunks x [128][40] fp16.
// ---------------------------------------------------------------------------
#define SM_A(st)   ((st) * 10240)
#define SM_W(st)   (20480 + (st) * 20480)
#define SM_H       61440
#define SM_B1      143360
#define SM_B2      144384
#define SM_G       145408
#define SM_BETA    146432
#define SM_PSUM    147456
#define SM_PSQ     147968
#define SMEM_T     148480

// ---------------------------------------------------------------------------
// Weight prep (4 weights, one launch): Wt[n][k] = fp16(W[k][n])
// ---------------------------------------------------------------------------
__global__ void wprep4_kernel(const float* __restrict__ W0,
                              const float* __restrict__ W1,
                              const float* __restrict__ W2,
                              const float* __restrict__ W3,
                              __half* __restrict__ base) {
    __shared__ float tile[32][33];
    const int which = blockIdx.x >> 6;
    const float* W = (which == 0) ? W0 : (which == 1) ? W1
                   : (which == 2) ? W2 : W3;
    __half* hi = base + (size_t)which * H * H;
    const int b  = blockIdx.x & 63;
    const int tx = threadIdx.x & 31;
    const int ty = threadIdx.x >> 5;
    const int bx = b & 7;
    const int by = b >> 3;
#pragma unroll
    for (int i = 0; i < 4; i++)
        tile[ty + i * 8][tx] = W[(by * 32 + ty + i * 8) * H + bx * 32 + tx];
    __syncthreads();
#pragma unroll
    for (int i = 0; i < 4; i++) {
        float v = tile[tx][ty + i * 8];
        int n = bx * 32 + ty + i * 8;
        int k = by * 32 + tx;
        hi[n * H + k] = __float2half_rn(v);
    }
}

// ---------------------------------------------------------------------------
// CSR build kernels
// ---------------------------------------------------------------------------
__global__ void zero2_kernel(int* __restrict__ a, int* __restrict__ b, int n) {
    int i = blockIdx.x * 256 + threadIdx.x;
    if (i < n) { a[i] = 0; b[i] = 0; }
}

__global__ void hist_kernel(const int* __restrict__ dst,
                            int* __restrict__ deg, int E) {
    int e = blockIdx.x * 256 + threadIdx.x;
    if (e < E) atomicAdd(&deg[__ldg(dst + e)], 1);
}

__global__ void blocksum_kernel(const int* __restrict__ deg,
                                int* __restrict__ part, int n) {
    __shared__ int ws[8];
    int b = blockIdx.x, t = threadIdx.x;
    int base = b * 1024 + t * 4;
    int s = 0;
#pragma unroll
    for (int j = 0; j < 4; j++)
        if (base + j < n) s += __ldg(deg + base + j);
#pragma unroll
    for (int o = 16; o > 0; o >>= 1) s += __shfl_down_sync(~0u, s, o);
    if ((t & 31) == 0) ws[t >> 5] = s;
    __syncthreads();
    if (t == 0) {
        int tot = 0;
#pragma unroll
        for (int w = 0; w < 8; w++) tot += ws[w];
        part[b] = tot;
    }
}

__global__ void scanpart_kernel(int* __restrict__ part, int nblk,
                                int* __restrict__ off, int n) {
    __shared__ int sh[128];
    int t = threadIdx.x;
    int v = (t < nblk) ? part[t] : 0;
    sh[t] = v;
    __syncthreads();
    for (int o = 1; o < 128; o <<= 1) {
        int u = (t >= o) ? sh[t - o] : 0;
        __syncthreads();
        sh[t] += u;
        __syncthreads();
    }
    if (t < nblk) part[t] = sh[t] - v;   // exclusive
    if (t == 127) off[n] = sh[127];
}

__global__ void scan3_kernel(const int* __restrict__ deg,
                             const int* __restrict__ part,
                             int* __restrict__ off, int n) {
    __shared__ int ws[8];
    int b = blockIdx.x, t = threadIdx.x;
    int lane = t & 31, w = t >> 5;
    int base = b * 1024 + t * 4;
    int v[4];
#pragma unroll
    for (int j = 0; j < 4; j++)
        v[j] = (base + j < n) ? __ldg(deg + base + j) : 0;
    int s = v[0] + v[1] + v[2] + v[3];
    int ss = s;
#pragma unroll
    for (int o = 1; o < 32; o <<= 1) {
        int u = __shfl_up_sync(~0u, ss, o);
        if (lane >= o) ss += u;
    }
    if (lane == 31) ws[w] = ss;
    __syncthreads();
    if (w == 0 && lane < 8) {
        int x = ws[lane];
#pragma unroll
        for (int o = 1; o < 8; o <<= 1) {
            int u = __shfl_up_sync(0xFFu, x, o);
            if (lane >= o) x += u;
        }
        ws[lane] = x;
    }
    __syncthreads();
    int run = ss - s + (w > 0 ? ws[w - 1] : 0) + __ldg(part + b);
#pragma unroll
    for (int j = 0; j < 4; j++) {
        if (base + j < n) off[base + j] = run;
        run += v[j];
    }
}

__global__ void fill_kernel(const int* __restrict__ src,
                            const int* __restrict__ dst,
                            const float* __restrict__ ea,
                            const int* __restrict__ off,
                            int* __restrict__ cnt,
                            int* __restrict__ csrc,
                            float* __restrict__ cea, int E) {
    int e = blockIdx.x * 256 + threadIdx.x;
    if (e >= E) return;
    int d = __ldg(dst + e);
    int pos = __ldg(off + d) + atomicAdd(&cnt[d], 1);
    csrc[pos] = __ldg(src + e);
    cea[pos]  = __ldg(ea + e);
}

// ---------------------------------------------------------------------------
// Aggregate + pack: axh[r] = fp16( x_dst[r] + sum relu(x_src + ea*We + be) )
// ---------------------------------------------------------------------------
__global__ void agg_kernel(const float* __restrict__ xsrc,
                           const float* __restrict__ xdst,
                           const int* __restrict__ off,
                           const int* __restrict__ csrc,
                           const float* __restrict__ cea,
                           const float* __restrict__ We,
                           const float* __restrict__ be,
                           uint32_t* __restrict__ axh, int M) {
    int r = blockIdx.x * 8 + (threadIdx.x >> 5);
    if (r >= M) return;
    int lane = threadIdx.x & 31;
    int col = lane * 8;

    float4 w0 = __ldg((const float4*)(We + col));
    float4 w1 = __ldg((const float4*)(We + col + 4));
    float4 b0 = __ldg((const float4*)(be + col));
    float4 b1 = __ldg((const float4*)(be + col + 4));

    const float4* dp = (const float4*)(xdst + (size_t)r * H + col);
    float4 d0 = dp[0], d1 = dp[1];
    float acc[8] = {d0.x, d0.y, d0.z, d0.w, d1.x, d1.y, d1.z, d1.w};

    int i  = __ldg(off + r);
    int s1 = __ldg(off + r + 1);

    int   sn = 0;
    float an = 0.f;
    if (i < s1) { sn = __ldg(csrc + i); an = __ldg(cea + i); }

    while (i < s1) {
        int s = sn; float a = an;
        i++;
        if (i < s1) { sn = __ldg(csrc + i); an = __ldg(cea + i); }

        const float4* xp = (const float4*)(xsrc + (size_t)s * H + col);
        float4 x0 = xp[0], x1 = xp[1];
        acc[0] += fmaxf(x0.x + fmaf(a, w0.x, b0.x), 0.f);
        acc[1] += fmaxf(x0.y + fmaf(a, w0.y, b0.y), 0.f);
        acc[2] += fmaxf(x0.z + fmaf(a, w0.z, b0.z), 0.f);
        acc[3] += fmaxf(x0.w + fmaf(a, w0.w, b0.w), 0.f);
        acc[4] += fmaxf(x1.x + fmaf(a, w1.x, b1.x), 0.f);
        acc[5] += fmaxf(x1.y + fmaf(a, w1.y, b1.y), 0.f);
        acc[6] += fmaxf(x1.z + fmaf(a, w1.z, b1.z), 0.f);
        acc[7] += fmaxf(x1.w + fmaf(a, w1.w, b1.w), 0.f);
    }

    uint4 o;
    o.x = pack2h(acc[0], acc[1]);
    o.y = pack2h(acc[2], acc[3]);
    o.z = pack2h(acc[4], acc[5]);
    o.w = pack2h(acc[6], acc[7]);
    *(uint4*)(axh + (size_t)r * (H / 2) + lane * 4) = o;
}

// ---------------------------------------------------------------------------
// Fused GINE MLP: out = LN( relu(axh@Wa + ba) @ Wb + bb + x ) * g + beta
// Pure fp16 single-pass MMA. Tile 128M x 256N, BK=32, 512 thr (16 warps,
// 4m x 4n, warp tile 32x64), 1 CTA/SM.
// ---------------------------------------------------------------------------
__global__ __launch_bounds__(512, 1) void fused_gine(
    const uint32_t* __restrict__ AXH, const float* __restrict__ X,
    const __half* __restrict__ Wa, const __half* __restrict__ Wb,
    const float* __restrict__ ba, const float* __restrict__ bb,
    const float* __restrict__ gln, const float* __restrict__ bln,
    float* __restrict__ C, int M)
{
    extern __shared__ char sm[];
    const uint32_t sb = smem_u32(sm);

    const int t = threadIdx.x;
    const int lane = t & 31;
    const int wid = t >> 5;
    const int wm = wid & 3;       // 4 m-warps (32 rows each)
    const int wn = wid >> 2;      // 4 n-warps (64 cols each)
    const int bm = blockIdx.x * 128;

    float* b1S  = (float*)(sm + SM_B1);
    float* b2S  = (float*)(sm + SM_B2);
    float* gS   = (float*)(sm + SM_G);
    float* bS   = (float*)(sm + SM_BETA);
    float* psum = (float*)(sm + SM_PSUM);
    float* psq  = (float*)(sm + SM_PSQ);

    if (t < 256) {
        b1S[t] = ba[t];
        b2S[t] = bb[t];
    } else {
        gS[t - 256] = gln[t - 256];
        bS[t - 256] = bln[t - 256];
    }
    if (t < 128) { psum[t] = 0.f; psq[t] = 0.f; }

    float c[2][8][4];
#pragma unroll
    for (int i = 0; i < 2; i++)
#pragma unroll
        for (int j = 0; j < 8; j++)
#pragma unroll
            for (int e = 0; e < 4; e++) c[i][j][e] = 0.f;

    // A chunk loader: 128 rows x 64B; thread -> (row = t>>2, seg = t&3)
    auto cpa = [&](int ck, int st) {
        const char* s = (const char*)AXH
                      + ((size_t)(bm + (t >> 2)) * 512) + ck * 64 + (t & 3) * 16;
        cp16(sb + SM_A(st) + (uint32_t)((t >> 2) * 80 + (t & 3) * 16), s);
    };
    // W chunk loader: 256 rows x 64B; thread -> (row = t>>1, half = t&1), 2x16B
    auto cpw = [&](const __half* W, int ck, int st) {
        const int row = t >> 1, hf = t & 1;
        const __half* s = W + (size_t)row * H + ck * 32 + hf * 16;
        uint32_t d = sb + SM_W(st) + row * 80 + hf * 32;
        cp16(d, s);
        cp16(d + 16, s + 8);
    };

    const uint32_t a_off = (uint32_t)((lane & 15) * 80 + (lane >> 4) * 16);
    const uint32_t w_off = (uint32_t)((wn * 64 + (lane & 7) + ((lane >> 4) * 8)) * 80
                                      + (((lane >> 3) & 1) * 16));

    auto compute = [&](uint32_t aBase, uint32_t wBase) {
        const uint32_t ah_base = aBase + (uint32_t)(wm * 2560) + a_off;
        const uint32_t wh_base = wBase + w_off;
#pragma unroll
        for (int ks = 0; ks < 2; ks++) {
            uint32_t ah0[4], ah1[4];
            uint32_t ab = ah_base + ks * 32;
            ldsm_x4(ah0, ab);
            ldsm_x4(ah1, ab + 1280);
            uint32_t bf[4][4];
            uint32_t wb = wh_base + ks * 32;
#pragma unroll
            for (int n4 = 0; n4 < 4; n4++) ldsm_x4(bf[n4], wb + n4 * 1280);
#pragma unroll
            for (int n4 = 0; n4 < 4; n4++) {
                const int nf = n4 * 2;
                mma_f16(c[0][nf],     ah0, bf[n4][0], bf[n4][1]);
                mma_f16(c[0][nf + 1], ah0, bf[n4][2], bf[n4][3]);
                mma_f16(c[1][nf],     ah1, bf[n4][0], bf[n4][1]);
                mma_f16(c[1][nf + 1], ah1, bf[n4][2], bf[n4][3]);
            }
        }
    };

    const int qrow = lane >> 2;
    const int qcol = lane & 3;

    // =================== Phase A: acc1 = AXH @ Wa ===================
    cpa(0, 0);
    cpw(Wa, 0, 0);
    CP_COMMIT();

#pragma unroll 1
    for (int ck = 0; ck < 8; ck++) {
        const int st = ck & 1;
        if (ck < 7) {
            cpa(ck + 1, st ^ 1);
            cpw(Wa, ck + 1, st ^ 1);
            CP_COMMIT();
            CP_WAIT1();
        } else {
            CP_WAIT0();
        }
        __syncthreads();
        compute(sb + SM_A(st), sb + SM_W(st));
        __syncthreads();
    }

    // ---- epilogue 1: h = relu(acc1 + ba) -> smem fp16 (A layout) ----
#pragma unroll
    for (int mf = 0; mf < 2; mf++)
#pragma unroll
        for (int rh = 0; rh < 2; rh++) {
            int r = wm * 32 + mf * 16 + rh * 8 + qrow;
#pragma unroll
            for (int nf = 0; nf < 8; nf++) {
                int kcol = wn * 64 + nf * 8 + qcol * 2;
                float z0 = fmaxf(c[mf][nf][rh * 2]     + b1S[kcol],     0.f);
                float z1 = fmaxf(c[mf][nf][rh * 2 + 1] + b1S[kcol + 1], 0.f);
                uint32_t off = (uint32_t)((kcol >> 5) * 10240 + r * 80
                                          + (kcol & 31) * 2);
                *(uint32_t*)(sm + SM_H + off) = pack2h(z0, z1);
            }
        }

#pragma unroll
    for (int i = 0; i < 2; i++)
#pragma unroll
        for (int j = 0; j < 8; j++)
#pragma unroll
            for (int e = 0; e < 4; e++) c[i][j][e] = 0.f;

    // =================== Phase B: acc2 = h @ Wb =========================
    cpw(Wb, 0, 0);
    CP_COMMIT();

#pragma unroll 1
    for (int ck = 0; ck < 8; ck++) {
        const int st = ck & 1;
        if (ck < 7) {
            cpw(Wb, ck + 1, st ^ 1);
            CP_COMMIT();
            CP_WAIT1();
        } else {
            CP_WAIT0();
        }
        __syncthreads();
        compute(sb + SM_H + ck * 10240, sb + SM_W(st));
        __syncthreads();
    }

    // ---- epilogue 2: LN(acc2 + bb + X) * g + beta ----
#pragma unroll
    for (int mf = 0; mf < 2; mf++)
#pragma unroll
        for (int rh = 0; rh < 2; rh++) {
            int r = wm * 32 + mf * 16 + rh * 8 + qrow;
            int grow = bm + r;
            float su = 0.f, sq = 0.f;
            if (grow < M) {
                const float* rrow = X + (size_t)grow * H;
#pragma unroll
                for (int nf = 0; nf < 8; nf++) {
                    int col = wn * 64 + nf * 8 + qcol * 2;
                    float2 rv = *(const float2*)(rrow + col);
                    float z0 = c[mf][nf][rh * 2]     + b2S[col]     + rv.x;
                    float z1 = c[mf][nf][rh * 2 + 1] + b2S[col + 1] + rv.y;
                    c[mf][nf][rh * 2]     = z0;
                    c[mf][nf][rh * 2 + 1] = z1;
                    su += z0 + z1;
                    sq += z0 * z0 + z1 * z1;
                }
            }
            su += __shfl_xor_sync(0xFFFFFFFFu, su, 1);
            su += __shfl_xor_sync(0xFFFFFFFFu, su, 2);
            sq += __shfl_xor_sync(0xFFFFFFFFu, sq, 1);
            sq += __shfl_xor_sync(0xFFFFFFFFu, sq, 2);
            if (qcol == 0 && grow < M) {
                atomicAdd(&psum[r], su);
                atomicAdd(&psq[r], sq);
            }
        }
    __syncthreads();
#pragma unroll
    for (int mf = 0; mf < 2; mf++)
#pragma unroll
        for (int rh = 0; rh < 2; rh++) {
            int r = wm * 32 + mf * 16 + rh * 8 + qrow;
            int grow = bm + r;
            if (grow >= M) continue;
            float mu = psum[r] * (1.f / 256.f);
            float var = psq[r] * (1.f / 256.f) - mu * mu;
            float rs = rsqrtf(var + LN_EPS);
            float* crow = C + (size_t)grow * H;
#pragma unroll
            for (int nf = 0; nf < 8; nf++) {
                int col = wn * 64 + nf * 8 + qcol * 2;
                float2 o;
                o.x = (c[mf][nf][rh * 2]     - mu) * rs * gS[col]     + bS[col];
                o.y = (c[mf][nf][rh * 2 + 1] - mu) * rs * gS[col + 1] + bS[col + 1];
                *(float2*)(crow + col) = o;
            }
        }
}

// ---------------------------------------------------------------------------
// launch
// ---------------------------------------------------------------------------
extern "C" void kernel_launch(void* const* d_in, const int* in_sizes, int n_in,
                              void* d_out, int out_size) {
    const float* x_var    = (const float*)d_in[0];
    const float* x_constr = (const float*)d_in[1];
    const int*   ei_v2c   = (const int*)  d_in[2];
    const int*   ei_c2v   = (const int*)  d_in[3];
    const float* ea       = (const float*)d_in[4];
    const float* We1 = (const float*)d_in[5];
    const float* be1 = (const float*)d_in[6];
    const float* W1a = (const float*)d_in[7];
    const float* b1a = (const float*)d_in[8];
    const float* W1b = (const float*)d_in[9];
    const float* b1b = (const float*)d_in[10];
    const float* We2 = (const float*)d_in[11];
    const float* be2 = (const float*)d_in[12];
    const float* W2a = (const float*)d_in[13];
    const float* b2a = (const float*)d_in[14];
    const float* W2b = (const float*)d_in[15];
    const float* b2b = (const float*)d_in[16];
    const float* g_constr    = (const float*)d_in[17];
    const float* beta_constr = (const float*)d_in[18];
    const float* g_var       = (const float*)d_in[19];
    const float* beta_var    = (const float*)d_in[20];

    const int NVr = in_sizes[0] / H;
    const int NCr = in_sizes[1] / H;
    const int Ecnt = in_sizes[4];

    uint32_t* axh;
    cudaGetSymbolAddress((void**)&axh, g_axh);
    __half* wt;
    cudaGetSymbolAddress((void**)&wt, g_wt);
    int *deg, *cnt, *off, *part, *csrc;
    float *cea;
    cudaGetSymbolAddress((void**)&deg, g_deg);
    cudaGetSymbolAddress((void**)&cnt, g_cnt);
    cudaGetSymbolAddress((void**)&off, g_off);
    cudaGetSymbolAddress((void**)&part, g_part);
    cudaGetSymbolAddress((void**)&csrc, g_csrc);
    cudaGetSymbolAddress((void**)&cea, g_cea);

    __half* wt1a = wt;
    __half* wt1b = wt + H * H;
    __half* wt2a = wt + 2 * H * H;
    __half* wt2b = wt + 3 * H * H;

    cudaFuncSetAttribute(fused_gine,
                         cudaFuncAttributeMaxDynamicSharedMemorySize, SMEM_T);

    float* out_var    = (float*)d_out;
    float* out_constr = (float*)d_out + (size_t)NVr * H;

    const int eb = (Ecnt + 255) / 256;

    wprep4_kernel<<<256, 256>>>(W1a, W1b, W2a, W2b, wt);

    // ---- stage 1: var -> constr ----
    {
        const int* src1 = ei_v2c;
        const int* dst1 = ei_v2c + Ecnt;
        int nblk = (NCr + 1023) / 1024;
        zero2_kernel<<<(NCr + 255) / 256, 256>>>(deg, cnt, NCr);
        hist_kernel<<<eb, 256>>>(dst1, deg, Ecnt);
        blocksum_kernel<<<nblk, 256>>>(deg, part, NCr);
        scanpart_kernel<<<1, 128>>>(part, nblk, off, NCr);
        scan3_kernel<<<nblk, 256>>>(deg, part, off, NCr);
        fill_kernel<<<eb, 256>>>(src1, dst1, ea, off, cnt, csrc, cea, Ecnt);
        agg_kernel<<<(NCr + 7) / 8, 256>>>(x_var, x_constr, off, csrc, cea,
                                           We1, be1, axh, NCr);
        int gx = (NCr + 127) / 128;
        fused_gine<<<gx, 512, SMEM_T>>>(
            axh, x_constr, wt1a, wt1b, b1a, b1b,
            g_constr, beta_constr, out_constr, NCr);
    }

    // ---- stage 2: constr -> var (reads LN'd x_constr from d_out) ----
    {
        const int* src2 = ei_c2v;
        const int* dst2 = ei_c2v + Ecnt;
        int nblk = (NVr + 1023) / 1024;
        zero2_kernel<<<(NVr + 255) / 256, 256>>>(deg, cnt, NVr);
        hist_kernel<<<eb, 256>>>(dst2, deg, Ecnt);
        blocksum_kernel<<<nblk, 256>>>(deg, part, NVr);
        scanpart_kernel<<<1, 128>>>(part, nblk, off, NVr);
        scan3_kernel<<<nblk, 256>>>(deg, part, off, NVr);
        fill_kernel<<<eb, 256>>>(src2, dst2, ea, off, cnt, csrc, cea, Ecnt);
        agg_kernel<<<(NVr + 7) / 8, 256>>>(out_constr, x_var, off, csrc, cea,
                                           We2, be2, axh, NVr);
        int gx = (NVr + 127) / 128;
        fused_gine<<<gx, 512, SMEM_T>>>(
            axh, x_var, wt2a, wt2b, b2a, b2b,
            g_var, beta_var, out_var, NVr);
    }
}

// round 14
// speedup vs baseline: 1.4282x; 1.0030x over previous
#include <cuda_runtime.h>
#include <cuda_fp16.h>
#include <cstdint>

#define H 256
#define MAXROWS 50000
#define NMAX 50048
#define EMAX 300000
#define NBLK 49                       // ceil(NMAX/1024)
#define LN_EPS 1e-5f

// ---------------------------------------------------------------------------
// Scratch (__device__ globals: allocation-free rule)
// ---------------------------------------------------------------------------
__device__ uint32_t g_xh [NMAX * (H / 2)];   // fp16x2 gather source
__device__ uint32_t g_axh[NMAX * (H / 2)];   // fp16x2 packed (x_dst + agg)
__device__ __half g_wt[4][H * H];            // transposed fp16 weights
__device__ int   g_deg [2 * NMAX];
__device__ int   g_cnt [2 * NMAX];
__device__ int   g_off [2 * (NMAX + 1)];
__device__ int   g_part[128];
__device__ int   g_csrc[2 * EMAX];
__device__ float g_cea [2 * EMAX];

// ---------------------------------------------------------------------------
// PTX helpers
// ---------------------------------------------------------------------------
__device__ __forceinline__ uint32_t smem_u32(const void* p) {
    uint32_t a;
    asm("{ .reg .u64 t; cvta.to.shared.u64 t, %1; cvt.u32.u64 %0, t; }"
        : "=r"(a) : "l"(p));
    return a;
}
__device__ __forceinline__ void ldsm_x4(uint32_t r[4], uint32_t addr) {
    asm volatile("ldmatrix.sync.aligned.m8n8.x4.shared.b16 {%0,%1,%2,%3}, [%4];"
                 : "=r"(r[0]), "=r"(r[1]), "=r"(r[2]), "=r"(r[3]) : "r"(addr));
}
__device__ __forceinline__ void mma_f16(float c[4],
                                        const uint32_t a[4],
                                        uint32_t b0, uint32_t b1) {
    asm volatile(
        "mma.sync.aligned.m16n8k16.row.col.f32.f16.f16.f32 "
        "{%0,%1,%2,%3}, {%4,%5,%6,%7}, {%8,%9}, {%0,%1,%2,%3};"
        : "+f"(c[0]), "+f"(c[1]), "+f"(c[2]), "+f"(c[3])
        : "r"(a[0]), "r"(a[1]), "r"(a[2]), "r"(a[3]), "r"(b0), "r"(b1));
}
__device__ __forceinline__ void cp16(uint32_t dst, const void* src) {
    asm volatile("cp.async.ca.shared.global [%0], [%1], 16;"
                 :: "r"(dst), "l"(src) : "memory");
}
#define CP_COMMIT() asm volatile("cp.async.commit_group;" ::: "memory")
#define CP_WAIT1()  asm volatile("cp.async.wait_group 1;" ::: "memory")
#define CP_WAIT0()  asm volatile("cp.async.wait_group 0;" ::: "memory")

__device__ __forceinline__ uint32_t pack2h(float a, float b) {
    __half2 h = __floats2half2_rn(a, b);
    return *(uint32_t*)&h;
}

// ---------------------------------------------------------------------------
// SMEM layout for fused_gine (bytes). M-tile = 128 rows.
// ---------------------------------------------------------------------------
#define SM_A(st)   ((st) * 10240)
#define SM_W(st)   (20480 + (st) * 20480)
#define SM_H       61440
#define SM_B1      143360
#define SM_B2      144384
#define SM_G       145408
#define SM_BETA    146432
#define SM_PSUM    147456
#define SM_PSQ     147968
#define SMEM_T     148480

// ---------------------------------------------------------------------------
// Weight prep (4 weights, one launch): Wt[n][k] = fp16(W[k][n])
// ---------------------------------------------------------------------------
__global__ void wprep4_kernel(const float* __restrict__ W0,
                              const float* __restrict__ W1,
                              const float* __restrict__ W2,
                              const float* __restrict__ W3,
                              __half* __restrict__ base) {
    __shared__ float tile[32][33];
    const int which = blockIdx.x >> 6;
    const float* W = (which == 0) ? W0 : (which == 1) ? W1
                   : (which == 2) ? W2 : W3;
    __half* hi = base + (size_t)which * H * H;
    const int b  = blockIdx.x & 63;
    const int tx = threadIdx.x & 31;
    const int ty = threadIdx.x >> 5;
    const int bx = b & 7;
    const int by = b >> 3;
#pragma unroll
    for (int i = 0; i < 4; i++)
        tile[ty + i * 8][tx] = W[(by * 32 + ty + i * 8) * H + bx * 32 + tx];
    __syncthreads();
#pragma unroll
    for (int i = 0; i < 4; i++) {
        float v = tile[tx][ty + i * 8];
        int n = bx * 32 + ty + i * 8;
        int k = by * 32 + tx;
        hi[n * H + k] = __float2half_rn(v);
    }
}

// ---------------------------------------------------------------------------
// fp32 -> packed fp16 conversion (for gather source)
// ---------------------------------------------------------------------------
__global__ void xconv_kernel(const float* __restrict__ x,
                             uint32_t* __restrict__ xh, int n32) {
    int i = blockIdx.x * 256 + threadIdx.x;
    if (i < n32) {
        float2 v = ((const float2*)x)[i];
        xh[i] = pack2h(v.x, v.y);
    }
}

// ---------------------------------------------------------------------------
// Batched CSR build (both stages at once; segment s in {0,1})
// ---------------------------------------------------------------------------
__global__ void zero2_kernel(int* __restrict__ a, int* __restrict__ b, int n) {
    int i = blockIdx.x * 256 + threadIdx.x;
    if (i < n) { a[i] = 0; b[i] = 0; }
}

__global__ void hist2_kernel(const int* __restrict__ d1,
                             const int* __restrict__ d2,
                             int* __restrict__ deg, int E) {
    int e = blockIdx.x * 256 + threadIdx.x;
    if (e < E)           atomicAdd(&deg[__ldg(d1 + e)], 1);
    else if (e < 2 * E)  atomicAdd(&deg[NMAX + __ldg(d2 + e - E)], 1);
}

__global__ void blocksum2_kernel(const int* __restrict__ deg,
                                 int* __restrict__ part, int n0, int n1) {
    __shared__ int ws[8];
    int seg = blockIdx.x / NBLK;
    int b   = blockIdx.x % NBLK;
    int n   = seg ? n1 : n0;
    const int* D = deg + seg * NMAX;
    int t = threadIdx.x;
    int base = b * 1024 + t * 4;
    int s = 0;
#pragma unroll
    for (int j = 0; j < 4; j++)
        if (base + j < n) s += __ldg(D + base + j);
#pragma unroll
    for (int o = 16; o > 0; o >>= 1) s += __shfl_down_sync(~0u, s, o);
    if ((t & 31) == 0) ws[t >> 5] = s;
    __syncthreads();
    if (t == 0) {
        int tot = 0;
#pragma unroll
        for (int w = 0; w < 8; w++) tot += ws[w];
        part[seg * 64 + b] = tot;
    }
}

__global__ void scanpart2_kernel(int* __restrict__ part,
                                 int* __restrict__ off, int n0, int n1) {
    __shared__ int sh[128];
    int seg = blockIdx.x;
    int n   = seg ? n1 : n0;
    int* P  = part + seg * 64;
    int* O  = off + seg * (NMAX + 1);
    int nblk = (n + 1023) >> 10;
    int t = threadIdx.x;
    int v = (t < nblk) ? P[t] : 0;
    sh[t] = v;
    __syncthreads();
    for (int o = 1; o < 128; o <<= 1) {
        int u = (t >= o) ? sh[t - o] : 0;
        __syncthreads();
        sh[t] += u;
        __syncthreads();
    }
    if (t < nblk) P[t] = sh[t] - v;      // exclusive
    if (t == 127) O[n] = sh[127];
}

__global__ void scan32_kernel(const int* __restrict__ deg,
                              const int* __restrict__ part,
                              int* __restrict__ off, int n0, int n1) {
    __shared__ int ws[8];
    int seg = blockIdx.x / NBLK;
    int b   = blockIdx.x % NBLK;
    int n   = seg ? n1 : n0;
    const int* D = deg + seg * NMAX;
    int* O  = off + seg * (NMAX + 1);
    int t = threadIdx.x;
    int lane = t & 31, w = t >> 5;
    int base = b * 1024 + t * 4;
    int v[4];
#pragma unroll
    for (int j = 0; j < 4; j++)
        v[j] = (base + j < n) ? __ldg(D + base + j) : 0;
    int s = v[0] + v[1] + v[2] + v[3];
    int ss = s;
#pragma unroll
    for (int o = 1; o < 32; o <<= 1) {
        int u = __shfl_up_sync(~0u, ss, o);
        if (lane >= o) ss += u;
    }
    if (lane == 31) ws[w] = ss;
    __syncthreads();
    if (w == 0 && lane < 8) {
        int x = ws[lane];
#pragma unroll
        for (int o = 1; o < 8; o <<= 1) {
            int u = __shfl_up_sync(0xFFu, x, o);
            if (lane >= o) x += u;
        }
        ws[lane] = x;
    }
    __syncthreads();
    int run = ss - s + (w > 0 ? ws[w - 1] : 0) + __ldg(part + seg * 64 + b);
#pragma unroll
    for (int j = 0; j < 4; j++) {
        if (base + j < n) O[base + j] = run;
        run += v[j];
    }
}

__global__ void fill2_kernel(const int* __restrict__ s1, const int* __restrict__ d1,
                             const int* __restrict__ s2, const int* __restrict__ d2,
                             const float* __restrict__ ea,
                             const int* __restrict__ off,
                             int* __restrict__ cnt,
                             int* __restrict__ csrc,
                             float* __restrict__ cea, int E) {
    int e = blockIdx.x * 256 + threadIdx.x;
    if (e >= 2 * E) return;
    int seg = (e >= E);
    int ee  = seg ? e - E : e;
    const int* sp = seg ? s2 : s1;
    const int* dp = seg ? d2 : d1;
    int d = __ldg(dp + ee);
    int pos = __ldg(off + seg * (NMAX + 1) + d)
            + atomicAdd(&cnt[seg * NMAX + d], 1);
    csrc[seg * EMAX + pos] = __ldg(sp + ee);
    cea [seg * EMAX + pos] = __ldg(ea + ee);
}

// ---------------------------------------------------------------------------
// Aggregate + pack: axh[r] = fp16( x_dst[r] + sum relu(xh_src + ea*We + be) )
// Warp per row; fp16 gather, fp32 accumulation.
// ---------------------------------------------------------------------------
__global__ void agg_kernel(const uint32_t* __restrict__ xh,
                           const float* __restrict__ xdst,
                           const int* __restrict__ off,
                           const int* __restrict__ csrc,
                           const float* __restrict__ cea,
                           const float* __restrict__ We,
                           const float* __restrict__ be,
                           uint32_t* __restrict__ axh, int M) {
    int r = blockIdx.x * 8 + (threadIdx.x >> 5);
    if (r >= M) return;
    int lane = threadIdx.x & 31;
    int col = lane * 8;

    float4 w0 = __ldg((const float4*)(We + col));
    float4 w1 = __ldg((const float4*)(We + col + 4));
    float4 b0 = __ldg((const float4*)(be + col));
    float4 b1 = __ldg((const float4*)(be + col + 4));

    const float4* dp = (const float4*)(xdst + (size_t)r * H + col);
    float4 d0 = dp[0], d1 = dp[1];
    float acc[8] = {d0.x, d0.y, d0.z, d0.w, d1.x, d1.y, d1.z, d1.w};

    int i  = __ldg(off + r);
    int s1 = __ldg(off + r + 1);

    int   sn = 0;
    float an = 0.f;
    if (i < s1) { sn = __ldg(csrc + i); an = __ldg(cea + i); }

    while (i < s1) {
        int s = sn; float a = an;
        i++;
        if (i < s1) { sn = __ldg(csrc + i); an = __ldg(cea + i); }

        uint4 xv = *(const uint4*)(xh + (size_t)s * (H / 2) + lane * 4);
        float2 f0 = __half22float2(*(__half2*)&xv.x);
        float2 f1 = __half22float2(*(__half2*)&xv.y);
        float2 f2 = __half22float2(*(__half2*)&xv.z);
        float2 f3 = __half22float2(*(__half2*)&xv.w);
        acc[0] += fmaxf(f0.x + fmaf(a, w0.x, b0.x), 0.f);
        acc[1] += fmaxf(f0.y + fmaf(a, w0.y, b0.y), 0.f);
        acc[2] += fmaxf(f1.x + fmaf(a, w0.z, b0.z), 0.f);
        acc[3] += fmaxf(f1.y + fmaf(a, w0.w, b0.w), 0.f);
        acc[4] += fmaxf(f2.x + fmaf(a, w1.x, b1.x), 0.f);
        acc[5] += fmaxf(f2.y + fmaf(a, w1.y, b1.y), 0.f);
        acc[6] += fmaxf(f3.x + fmaf(a, w1.z, b1.z), 0.f);
        acc[7] += fmaxf(f3.y + fmaf(a, w1.w, b1.w), 0.f);
    }

    uint4 o;
    o.x = pack2h(acc[0], acc[1]);
    o.y = pack2h(acc[2], acc[3]);
    o.z = pack2h(acc[4], acc[5]);
    o.w = pack2h(acc[6], acc[7]);
    *(uint4*)(axh + (size_t)r * (H / 2) + lane * 4) = o;
}

// ---------------------------------------------------------------------------
// Fused GINE MLP: out = LN( relu(axh@Wa + ba) @ Wb + bb + x ) * g + beta
// Tile 128M x 256N, BK=32, 512 thr (16 warps, 4m x 4n), 1 CTA/SM.
// Optionally also emits fp16 copy of out (XHo) for the next gather stage.
// ---------------------------------------------------------------------------
__global__ __launch_bounds__(512, 1) void fused_gine(
    const uint32_t* __restrict__ AXH, const float* __restrict__ X,
    const __half* __restrict__ Wa, const __half* __restrict__ Wb,
    const float* __restrict__ ba, const float* __restrict__ bb,
    const float* __restrict__ gln, const float* __restrict__ bln,
    float* __restrict__ C, uint32_t* __restrict__ XHo, int M)
{
    extern __shared__ char sm[];
    const uint32_t sb = smem_u32(sm);

    const int t = threadIdx.x;
    const int lane = t & 31;
    const int wid = t >> 5;
    const int wm = wid & 3;       // 4 m-warps
    const int wn = wid >> 2;      // 4 n-warps
    const int bm = blockIdx.x * 128;

    float* b1S  = (float*)(sm + SM_B1);
    float* b2S  = (float*)(sm + SM_B2);
    float* gS   = (float*)(sm + SM_G);
    float* bS   = (float*)(sm + SM_BETA);
    float* psum = (float*)(sm + SM_PSUM);
    float* psq  = (float*)(sm + SM_PSQ);

    if (t < 256) {
        b1S[t] = ba[t];
        b2S[t] = bb[t];
    } else {
        gS[t - 256] = gln[t - 256];
        bS[t - 256] = bln[t - 256];
    }
    if (t < 128) { psum[t] = 0.f; psq[t] = 0.f; }

    float c[2][8][4];
#pragma unroll
    for (int i = 0; i < 2; i++)
#pragma unroll
        for (int j = 0; j < 8; j++)
#pragma unroll
            for (int e = 0; e < 4; e++) c[i][j][e] = 0.f;

    auto cpa = [&](int ck, int st) {
        const char* s = (const char*)AXH
                      + ((size_t)(bm + (t >> 2)) * 512) + ck * 64 + (t & 3) * 16;
        cp16(sb + SM_A(st) + (uint32_t)((t >> 2) * 80 + (t & 3) * 16), s);
    };
    auto cpw = [&](const __half* W, int ck, int st) {
        const int row = t >> 1, hf = t & 1;
        const __half* s = W + (size_t)row * H + ck * 32 + hf * 16;
        uint32_t d = sb + SM_W(st) + row * 80 + hf * 32;
        cp16(d, s);
        cp16(d + 16, s + 8);
    };

    const uint32_t a_off = (uint32_t)((lane & 15) * 80 + (lane >> 4) * 16);
    const uint32_t w_off = (uint32_t)((wn * 64 + (lane & 7) + ((lane >> 4) * 8)) * 80
                                      + (((lane >> 3) & 1) * 16));

    auto compute = [&](uint32_t aBase, uint32_t wBase) {
        const uint32_t ah_base = aBase + (uint32_t)(wm * 2560) + a_off;
        const uint32_t wh_base = wBase + w_off;
#pragma unroll
        for (int ks = 0; ks < 2; ks++) {
            uint32_t ah0[4], ah1[4];
            uint32_t ab = ah_base + ks * 32;
            ldsm_x4(ah0, ab);
            ldsm_x4(ah1, ab + 1280);
            uint32_t bf[4][4];
            uint32_t wb = wh_base + ks * 32;
#pragma unroll
            for (int n4 = 0; n4 < 4; n4++) ldsm_x4(bf[n4], wb + n4 * 1280);
#pragma unroll
            for (int n4 = 0; n4 < 4; n4++) {
                const int nf = n4 * 2;
                mma_f16(c[0][nf],     ah0, bf[n4][0], bf[n4][1]);
                mma_f16(c[0][nf + 1], ah0, bf[n4][2], bf[n4][3]);
                mma_f16(c[1][nf],     ah1, bf[n4][0], bf[n4][1]);
                mma_f16(c[1][nf + 1], ah1, bf[n4][2], bf[n4][3]);
            }
        }
    };

    const int qrow = lane >> 2;
    const int qcol = lane & 3;

    // =================== Phase A: acc1 = AXH @ Wa ===================
    cpa(0, 0);
    cpw(Wa, 0, 0);
    CP_COMMIT();

#pragma unroll 1
    for (int ck = 0; ck < 8; ck++) {
        const int st = ck & 1;
        if (ck < 7) {
            cpa(ck + 1, st ^ 1);
            cpw(Wa, ck + 1, st ^ 1);
            CP_COMMIT();
            CP_WAIT1();
        } else {
            CP_WAIT0();
        }
        __syncthreads();
        compute(sb + SM_A(st), sb + SM_W(st));
        __syncthreads();
    }

    // ---- epilogue 1: h = relu(acc1 + ba) -> smem fp16 (A layout) ----
#pragma unroll
    for (int mf = 0; mf < 2; mf++)
#pragma unroll
        for (int rh = 0; rh < 2; rh++) {
            int r = wm * 32 + mf * 16 + rh * 8 + qrow;
#pragma unroll
            for (int nf = 0; nf < 8; nf++) {
                int kcol = wn * 64 + nf * 8 + qcol * 2;
                float z0 = fmaxf(c[mf][nf][rh * 2]     + b1S[kcol],     0.f);
                float z1 = fmaxf(c[mf][nf][rh * 2 + 1] + b1S[kcol + 1], 0.f);
                uint32_t off = (uint32_t)((kcol >> 5) * 10240 + r * 80
                                          + (kcol & 31) * 2);
                *(uint32_t*)(sm + SM_H + off) = pack2h(z0, z1);
            }
        }

#pragma unroll
    for (int i = 0; i < 2; i++)
#pragma unroll
        for (int j = 0; j < 8; j++)
#pragma unroll
            for (int e = 0; e < 4; e++) c[i][j][e] = 0.f;

    // =================== Phase B: acc2 = h @ Wb =========================
    cpw(Wb, 0, 0);
    CP_COMMIT();

#pragma unroll 1
    for (int ck = 0; ck < 8; ck++) {
        const int st = ck & 1;
        if (ck < 7) {
            cpw(Wb, ck + 1, st ^ 1);
            CP_COMMIT();
            CP_WAIT1();
        } else {
            CP_WAIT0();
        }
        __syncthreads();
        compute(sb + SM_H + ck * 10240, sb + SM_W(st));
        __syncthreads();
    }

    // ---- epilogue 2: LN(acc2 + bb + X) * g + beta ----
#pragma unroll
    for (int mf = 0; mf < 2; mf++)
#pragma unroll
        for (int rh = 0; rh < 2; rh++) {
            int r = wm * 32 + mf * 16 + rh * 8 + qrow;
            int grow = bm + r;
            float su = 0.f, sq = 0.f;
            if (grow < M) {
                const float* rrow = X + (size_t)grow * H;
#pragma unroll
                for (int nf = 0; nf < 8; nf++) {
                    int col = wn * 64 + nf * 8 + qcol * 2;
                    float2 rv = *(const float2*)(rrow + col);
                    float z0 = c[mf][nf][rh * 2]     + b2S[col]     + rv.x;
                    float z1 = c[mf][nf][rh * 2 + 1] + b2S[col + 1] + rv.y;
                    c[mf][nf][rh * 2]     = z0;
                    c[mf][nf][rh * 2 + 1] = z1;
                    su += z0 + z1;
                    sq += z0 * z0 + z1 * z1;
                }
            }
            su += __shfl_xor_sync(0xFFFFFFFFu, su, 1);
            su += __shfl_xor_sync(0xFFFFFFFFu, su, 2);
            sq += __shfl_xor_sync(0xFFFFFFFFu, sq, 1);
            sq += __shfl_xor_sync(0xFFFFFFFFu, sq, 2);
            if (qcol == 0 && grow < M) {
                atomicAdd(&psum[r], su);
                atomicAdd(&psq[r], sq);
            }
        }
    __syncthreads();
#pragma unroll
    for (int mf = 0; mf < 2; mf++)
#pragma unroll
        for (int rh = 0; rh < 2; rh++) {
            int r = wm * 32 + mf * 16 + rh * 8 + qrow;
            int grow = bm + r;
            if (grow >= M) continue;
            float mu = psum[r] * (1.f / 256.f);
            float var = psq[r] * (1.f / 256.f) - mu * mu;
            float rs = rsqrtf(var + LN_EPS);
            float* crow = C + (size_t)grow * H;
            uint32_t* hrow = XHo ? XHo + (size_t)grow * (H / 2) : nullptr;
#pragma unroll
            for (int nf = 0; nf < 8; nf++) {
                int col = wn * 64 + nf * 8 + qcol * 2;
                float2 o;
                o.x = (c[mf][nf][rh * 2]     - mu) * rs * gS[col]     + bS[col];
                o.y = (c[mf][nf][rh * 2 + 1] - mu) * rs * gS[col + 1] + bS[col + 1];
                *(float2*)(crow + col) = o;
                if (XHo) hrow[col >> 1] = pack2h(o.x, o.y);
            }
        }
}

// ---------------------------------------------------------------------------
// launch
// ---------------------------------------------------------------------------
extern "C" void kernel_launch(void* const* d_in, const int* in_sizes, int n_in,
                              void* d_out, int out_size) {
    const float* x_var    = (const float*)d_in[0];
    const float* x_constr = (const float*)d_in[1];
    const int*   ei_v2c   = (const int*)  d_in[2];
    const int*   ei_c2v   = (const int*)  d_in[3];
    const float* ea       = (const float*)d_in[4];
    const float* We1 = (const float*)d_in[5];
    const float* be1 = (const float*)d_in[6];
    const float* W1a = (const float*)d_in[7];
    const float* b1a = (const float*)d_in[8];
    const float* W1b = (const float*)d_in[9];
    const float* b1b = (const float*)d_in[10];
    const float* We2 = (const float*)d_in[11];
    const float* be2 = (const float*)d_in[12];
    const float* W2a = (const float*)d_in[13];
    const float* b2a = (const float*)d_in[14];
    const float* W2b = (const float*)d_in[15];
    const float* b2b = (const float*)d_in[16];
    const float* g_constr    = (const float*)d_in[17];
    const float* beta_constr = (const float*)d_in[18];
    const float* g_var       = (const float*)d_in[19];
    const float* beta_var    = (const float*)d_in[20];

    const int NVr = in_sizes[0] / H;
    const int NCr = in_sizes[1] / H;
    const int Ecnt = in_sizes[4];

    uint32_t *xh, *axh;
    cudaGetSymbolAddress((void**)&xh,  g_xh);
    cudaGetSymbolAddress((void**)&axh, g_axh);
    __half* wt;
    cudaGetSymbolAddress((void**)&wt, g_wt);
    int *deg, *cnt, *off, *part, *csrc;
    float *cea;
    cudaGetSymbolAddress((void**)&deg, g_deg);
    cudaGetSymbolAddress((void**)&cnt, g_cnt);
    cudaGetSymbolAddress((void**)&off, g_off);
    cudaGetSymbolAddress((void**)&part, g_part);
    cudaGetSymbolAddress((void**)&csrc, g_csrc);
    cudaGetSymbolAddress((void**)&cea, g_cea);

    __half* wt1a = wt;
    __half* wt1b = wt + H * H;
    __half* wt2a = wt + 2 * H * H;
    __half* wt2b = wt + 3 * H * H;

    cudaFuncSetAttribute(fused_gine,
                         cudaFuncAttributeMaxDynamicSharedMemorySize, SMEM_T);

    float* out_var    = (float*)d_out;
    float* out_constr = (float*)d_out + (size_t)NVr * H;

    const int* src1 = ei_v2c;               // stage 1: var -> constr
    const int* dst1 = ei_v2c + Ecnt;
    const int* src2 = ei_c2v;               // stage 2: constr -> var
    const int* dst2 = ei_c2v + Ecnt;

    // ---- prep: weights, fp16 x_var, both CSRs ----
    wprep4_kernel<<<256, 256>>>(W1a, W1b, W2a, W2b, wt);
    xconv_kernel<<<(NVr * (H / 2) + 255) / 256, 256>>>(x_var, xh, NVr * (H / 2));

    zero2_kernel<<<(2 * NMAX + 255) / 256, 256>>>(deg, cnt, 2 * NMAX);
    hist2_kernel<<<(2 * Ecnt + 255) / 256, 256>>>(dst1, dst2, deg, Ecnt);
    blocksum2_kernel<<<2 * NBLK, 256>>>(deg, part, NCr, NVr);
    scanpart2_kernel<<<2, 128>>>(part, off, NCr, NVr);
    scan32_kernel<<<2 * NBLK, 256>>>(deg, part, off, NCr, NVr);
    fill2_kernel<<<(2 * Ecnt + 255) / 256, 256>>>(src1, dst1, src2, dst2,
                                                  ea, off, cnt, csrc, cea, Ecnt);

    // ---- stage 1: var -> constr (writes out_constr + fp16 copy into xh) ----
    agg_kernel<<<(NCr + 7) / 8, 256>>>(xh, x_constr, off, csrc, cea,
                                       We1, be1, axh, NCr);
    fused_gine<<<(NCr + 127) / 128, 512, SMEM_T>>>(
        axh, x_constr, wt1a, wt1b, b1a, b1b,
        g_constr, beta_constr, out_constr, xh, NCr);

    // ---- stage 2: constr -> var ----
    agg_kernel<<<(NVr + 7) / 8, 256>>>(xh, x_var,
                                       off + (NMAX + 1), csrc + EMAX, cea + EMAX,
                                       We2, be2, axh, NVr);
    fused_gine<<<(NVr + 127) / 128, 512, SMEM_T>>>(
        axh, x_var, wt2a, wt2b, b2a, b2b,
        g_var, beta_var, out_var, nullptr, NVr);
}